// round 10
// baseline (speedup 1.0000x reference)
#include <cuda_runtime.h>
#include <math.h>
#include <stdint.h>

#define BSZ 16
#define NN 768
#define INDIM 16
#define HID 64
#define EMB 128
#define NH 8
#define BN (BSZ*NN)        // 12288
#define FDIM (NH*HID)      // 512
#define BH (BSZ*NH)        // 128
#define BHN (BH*NN)        // 98304
#define CH 96
#define NCH 8              // CH*NCH = 768

// ---- static scratch ----
__device__ float g_h0 [BN*HID];
__device__ float g_Wh [BN*FDIM];
__device__ float g_hc1[BN*FDIM];
__device__ float g_hc2[BN*FDIM];
__device__ float g_s1[BHN], g_s2[BHN];
__device__ float g_E2s[BHN], g_F2s[BHN];
__device__ int   g_perm[BHN];
__device__ int   g_kofn[BHN];
__device__ float g_s2max[BH];
__device__ float g_preF2[BH*(NN+1)], g_sufE2[BH*(NN+1)];
__device__ float g_B0t[FDIM*HID];
__device__ float g_B1t[FDIM*FDIM];
__device__ float g_pwT[EMB*FDIM];

// ===================== HMMA tf32 GEMM (+ fused score) =====================
__device__ __forceinline__ uint32_t smem_u32(const void* p) {
    uint32_t a;
    asm("{ .reg .u64 t; cvta.to.shared.u64 t, %1; cvt.u32.u64 %0, t; }" : "=r"(a) : "l"(p));
    return a;
}
__device__ __forceinline__ uint32_t f2tf(float x) {
    uint32_t u; asm("cvt.rna.tf32.f32 %0, %1;" : "=r"(u) : "f"(x)); return u;
}
__device__ __forceinline__ void mma_tf32(float* d, const uint32_t* a, const uint32_t* b) {
    asm volatile("mma.sync.aligned.m16n8k8.row.col.f32.tf32.tf32.f32 "
                 "{%0,%1,%2,%3}, {%4,%5,%6,%7}, {%8,%9}, {%0,%1,%2,%3};"
                 : "+f"(d[0]), "+f"(d[1]), "+f"(d[2]), "+f"(d[3])
                 : "r"(a[0]), "r"(a[1]), "r"(a[2]), "r"(a[3]), "r"(b[0]), "r"(b[1]));
}
#define CP16(dst, src) \
    asm volatile("cp.async.ca.shared.global [%0], [%1], 16;" :: "r"(dst), "l"(src) : "memory")
#define CP_COMMIT()  asm volatile("cp.async.commit_group;" ::: "memory")
#define CP_WAIT0()   asm volatile("cp.async.wait_group 0;" ::: "memory")

__device__ __forceinline__ int swz(int row, int k) {
    return row * 32 + ((((k >> 2) ^ (row & 7)) << 2) | (k & 3));
}

__global__ __launch_bounds__(128)
void tf32_gemm(const float* __restrict__ A, const float* __restrict__ Bt,
               const float* __restrict__ bias, float* __restrict__ C,
               int N, int K,
               const float* __restrict__ att, float* __restrict__ s1out,
               float* __restrict__ s2out) {
    __shared__ float As[2][128 * 32];
    __shared__ float Bs[2][64 * 32];
    __shared__ float sp1[128], sp2[128];
    const int tid = threadIdx.x;
    const int wid = tid >> 5, lane = tid & 31;
    const int r = lane >> 2, cc = lane & 3;
    const int warp_m = (wid & 1) * 64, warp_n = (wid >> 1) * 32;
    const int m0 = blockIdx.x * 128, n0 = blockIdx.y * 64;

    sp1[tid] = 0.f; sp2[tid] = 0.f;

    uint32_t asb[2] = { smem_u32(&As[0][0]), smem_u32(&As[1][0]) };
    uint32_t bsb[2] = { smem_u32(&Bs[0][0]), smem_u32(&Bs[1][0]) };

    float acc[4][4][4] = {};
    const int NC = K >> 5;

    {
#pragma unroll
        for (int j = 0; j < 8; j++) {
            int u = tid + j * 128, row = u >> 3, ch = u & 7;
            CP16(asb[0] + (uint32_t)(row * 32 + ((ch ^ (row & 7)) << 2)) * 4,
                 A + (size_t)(m0 + row) * K + ch * 4);
        }
#pragma unroll
        for (int j = 0; j < 4; j++) {
            int u = tid + j * 128, row = u >> 3, ch = u & 7;
            CP16(bsb[0] + (uint32_t)(row * 32 + ((ch ^ (row & 7)) << 2)) * 4,
                 Bt + (size_t)(n0 + row) * K + ch * 4);
        }
        CP_COMMIT();
    }

    for (int i = 0; i < NC; i++) {
        CP_WAIT0();
        __syncthreads();
        if (i + 1 < NC) {
            int nb = (i + 1) & 1, kc = (i + 1) * 32;
#pragma unroll
            for (int j = 0; j < 8; j++) {
                int u = tid + j * 128, row = u >> 3, ch = u & 7;
                CP16(asb[nb] + (uint32_t)(row * 32 + ((ch ^ (row & 7)) << 2)) * 4,
                     A + (size_t)(m0 + row) * K + kc + ch * 4);
            }
#pragma unroll
            for (int j = 0; j < 4; j++) {
                int u = tid + j * 128, row = u >> 3, ch = u & 7;
                CP16(bsb[nb] + (uint32_t)(row * 32 + ((ch ^ (row & 7)) << 2)) * 4,
                     Bt + (size_t)(n0 + row) * K + kc + ch * 4);
            }
            CP_COMMIT();
        }
        const float* as = As[i & 1];
        const float* bs = Bs[i & 1];
#pragma unroll
        for (int ks = 0; ks < 4; ks++) {
            uint32_t af[4][4], bf[4][2];
#pragma unroll
            for (int mt = 0; mt < 4; mt++) {
                int rb = warp_m + mt * 16 + r;
                af[mt][0] = f2tf(as[swz(rb,     ks * 8 + cc)]);
                af[mt][1] = f2tf(as[swz(rb + 8, ks * 8 + cc)]);
                af[mt][2] = f2tf(as[swz(rb,     ks * 8 + cc + 4)]);
                af[mt][3] = f2tf(as[swz(rb + 8, ks * 8 + cc + 4)]);
            }
#pragma unroll
            for (int nt = 0; nt < 4; nt++) {
                int nb = warp_n + nt * 8 + r;
                bf[nt][0] = f2tf(bs[swz(nb, ks * 8 + cc)]);
                bf[nt][1] = f2tf(bs[swz(nb, ks * 8 + cc + 4)]);
            }
#pragma unroll
            for (int mt = 0; mt < 4; mt++)
#pragma unroll
                for (int nt = 0; nt < 4; nt++)
                    mma_tf32(acc[mt][nt], af[mt], bf[nt]);
        }
        __syncthreads();
    }

#pragma unroll
    for (int mt = 0; mt < 4; mt++) {
#pragma unroll
        for (int nt = 0; nt < 4; nt++) {
            int row = m0 + warp_m + mt * 16 + r;
            int col = n0 + warp_n + nt * 8 + cc * 2;
            float bx = 0.f, by = 0.f;
            if (bias) { bx = bias[col]; by = bias[col + 1]; }
            float2 v0 = { acc[mt][nt][0] + bx, acc[mt][nt][1] + by };
            float2 v1 = { acc[mt][nt][2] + bx, acc[mt][nt][3] + by };
            *(float2*)&C[(size_t)row * N + col] = v0;
            *(float2*)&C[(size_t)(row + 8) * N + col] = v1;
        }
    }

    if (att) {
        int h = n0 >> 6;
        const float* a1 = att + h * 2 * HID;
        const float* a2 = a1 + HID;
#pragma unroll
        for (int mt = 0; mt < 4; mt++) {
            float p1a = 0.f, p2a = 0.f, p1b = 0.f, p2b = 0.f;
#pragma unroll
            for (int nt = 0; nt < 4; nt++) {
                int col = warp_n + nt * 8 + cc * 2;
                float a1x = a1[col], a1y = a1[col + 1];
                float a2x = a2[col], a2y = a2[col + 1];
                p1a += acc[mt][nt][0] * a1x + acc[mt][nt][1] * a1y;
                p2a += acc[mt][nt][0] * a2x + acc[mt][nt][1] * a2y;
                p1b += acc[mt][nt][2] * a1x + acc[mt][nt][3] * a1y;
                p2b += acc[mt][nt][2] * a2x + acc[mt][nt][3] * a2y;
            }
#pragma unroll
            for (int off = 1; off <= 2; off <<= 1) {
                p1a += __shfl_xor_sync(0xffffffffu, p1a, off);
                p2a += __shfl_xor_sync(0xffffffffu, p2a, off);
                p1b += __shfl_xor_sync(0xffffffffu, p1b, off);
                p2b += __shfl_xor_sync(0xffffffffu, p2b, off);
            }
            if (cc == 0) {
                int lr = warp_m + mt * 16 + r;
                atomicAdd(&sp1[lr], p1a);     atomicAdd(&sp2[lr], p2a);
                atomicAdd(&sp1[lr + 8], p1b); atomicAdd(&sp2[lr + 8], p2b);
            }
        }
        __syncthreads();
        int gr = m0 + tid;
        int b2 = gr / NN, n2 = gr % NN;
        int bh2 = b2 * NH + h;
        s1out[bh2 * NN + n2] = sp1[tid];
        s2out[bh2 * NN + n2] = sp2[tid];
    }
}

// ===================== non-GEMM kernels =====================

__global__ void prep_B(const float* __restrict__ w0, const float* __restrict__ w1,
                       const float* __restrict__ pw) {
    int i0 = blockIdx.x * blockDim.x + threadIdx.x;
    int stride = gridDim.x * blockDim.x;
    for (int i = i0; i < FDIM*HID; i += stride) {
        int n = i / HID, f = i % HID;
        g_B0t[i] = w0[(n / HID) * (HID*HID) + f * HID + (n % HID)];
    }
    for (int i = i0; i < FDIM*FDIM; i += stride) {
        int n = i / FDIM, f = i % FDIM;
        g_B1t[i] = w1[(n / HID) * (FDIM*HID) + f * HID + (n % HID)];
    }
    for (int i = i0; i < EMB*FDIM; i += stride) {
        int n = i / FDIM, k = i % FDIM;
        g_pwT[i] = pw[k * EMB + n];
    }
}

// small fp32 SGEMM for the input projection (K=16)
__global__ void sgemm(const float* __restrict__ A, const float* __restrict__ B,
                      const float* __restrict__ bias, float* __restrict__ C,
                      int M, int N, int K) {
    __shared__ float As[16][64];
    __shared__ float Bs[16][64];
    int tid = threadIdx.x;
    int m0 = blockIdx.x * 64, n0 = blockIdx.y * 64;
    int tx = tid & 15, ty = tid >> 4;
    int arow = tid >> 2, acol = (tid & 3) * 4;
    int brow = tid >> 4, bcol = (tid & 15) * 4;
    float acc[4][4] = {};
    for (int kc = 0; kc < K; kc += 16) {
        float4 av = *(const float4*)&A[(size_t)(m0 + arow) * K + kc + acol];
        As[acol+0][arow] = av.x; As[acol+1][arow] = av.y;
        As[acol+2][arow] = av.z; As[acol+3][arow] = av.w;
        *(float4*)&Bs[brow][bcol] = *(const float4*)&B[(size_t)(kc + brow) * N + n0 + bcol];
        __syncthreads();
#pragma unroll
        for (int k = 0; k < 16; k++) {
            float4 a4 = *(float4*)&As[k][ty*4];
            float4 b4 = *(float4*)&Bs[k][tx*4];
            float a[4] = {a4.x, a4.y, a4.z, a4.w};
            float b[4] = {b4.x, b4.y, b4.z, b4.w};
#pragma unroll
            for (int i = 0; i < 4; i++)
#pragma unroll
                for (int j = 0; j < 4; j++) acc[i][j] += a[i] * b[j];
        }
        __syncthreads();
    }
#pragma unroll
    for (int i = 0; i < 4; i++) {
        int m = m0 + ty*4 + i, n = n0 + tx*4;
        float4 v = {acc[i][0], acc[i][1], acc[i][2], acc[i][3]};
        if (bias) { v.x += bias[n]; v.y += bias[n+1]; v.z += bias[n+2]; v.w += bias[n+3]; }
        *(float4*)&C[(size_t)m * N + n] = v;
    }
}

// Per (b,h): u64-packed bitonic sort of s2 (key|idx), E2/F2, parallel scans,
// k(n) via binary search.
__global__ __launch_bounds__(512)
void sort_prep(const float* __restrict__ s2, const float* __restrict__ s1) {
    __shared__ unsigned long long sv[1024];
    __shared__ float fe[NN], ff[NN], s2c[NN];
    __shared__ float wsE[16], wsF[16];
    int bh = blockIdx.x, tid = threadIdx.x;
    int lane = tid & 31, wrp = tid >> 5;

    for (int i = tid; i < 1024; i += 512) {
        if (i < NN) {
            uint32_t bt = __float_as_uint(s2[bh*NN + i]);
            uint32_t key = (bt & 0x80000000u) ? ~bt : (bt | 0x80000000u);
            sv[i] = ((unsigned long long)key << 32) | (unsigned)i;
        } else sv[i] = 0xFFFFFFFFFFFFFFFFull;
    }
    __syncthreads();
    for (int k = 2; k <= 1024; k <<= 1) {
        for (int j = k >> 1; j > 0; j >>= 1) {
            for (int i = tid; i < 1024; i += 512) {
                int ixj = i ^ j;
                if (ixj > i) {
                    bool up = ((i & k) == 0);
                    unsigned long long a = sv[i], b = sv[ixj];
                    if ((a > b) == up) { sv[i] = b; sv[ixj] = a; }
                }
            }
            __syncthreads();
        }
    }
    float mx;
    {
        uint32_t keyN = (uint32_t)(sv[NN-1] >> 32);
        uint32_t bt = (keyN & 0x80000000u) ? (keyN & 0x7FFFFFFFu) : ~keyN;
        mx = __uint_as_float(bt);
    }
    if (tid == 0) g_s2max[bh] = mx;
    for (int i = tid; i < NN; i += 512) {
        unsigned long long p = sv[i];
        uint32_t key = (uint32_t)(p >> 32);
        uint32_t bt = (key & 0x80000000u) ? (key & 0x7FFFFFFFu) : ~key;
        float v = __uint_as_float(bt);
        float d = v - mx;
        float e = expf(d), f = expf(0.2f * d);
        fe[i] = e; ff[i] = f;
        s2c[i] = v;
        g_E2s[bh*NN + i] = e;
        g_F2s[bh*NN + i] = f;
        g_perm[bh*NN + i] = (int)(p & 0xFFFFFFFFu);
    }
    __syncthreads();

    int i0 = 2 * tid, i1 = 2 * tid + 1;
    float e0 = (i0 < NN) ? fe[i0] : 0.f, e1 = (i1 < NN) ? fe[i1] : 0.f;
    float f0 = (i0 < NN) ? ff[i0] : 0.f, f1 = (i1 < NN) ? ff[i1] : 0.f;
    float le = e0 + e1, lf = f0 + f1;
    float eI = le, fI = lf;
#pragma unroll
    for (int off = 1; off < 32; off <<= 1) {
        float a = __shfl_up_sync(0xffffffffu, eI, off);
        float b = __shfl_up_sync(0xffffffffu, fI, off);
        if (lane >= off) { eI += a; fI += b; }
    }
    if (lane == 31) { wsE[wrp] = eI; wsF[wrp] = fI; }
    __syncthreads();
    if (tid == 0) {
        float a = 0.f, b = 0.f;
        for (int w = 0; w < 16; w++) { a += wsE[w]; wsE[w] = a; b += wsF[w]; wsF[w] = b; }
    }
    __syncthreads();
    float baseE = (wrp > 0) ? wsE[wrp-1] : 0.f;
    float baseF = (wrp > 0) ? wsF[wrp-1] : 0.f;
    float eexcl = baseE + (eI - le);
    float fexcl = baseF + (fI - lf);
    float totE = wsE[15], totF = wsF[15];
    int base = bh * (NN + 1);
    if (i0 < NN) { g_preF2[base + i0] = fexcl;      g_sufE2[base + i0] = totE - eexcl; }
    if (i1 < NN) { g_preF2[base + i1] = fexcl + f0; g_sufE2[base + i1] = totE - (eexcl + e0); }
    if (tid == 0) { g_preF2[base + NN] = totF; g_sufE2[base + NN] = 0.f; }

    for (int n = tid; n < NN; n += 512) {
        float thr = -s1[bh*NN + n];
        int lo = 0, hi = NN;
        while (lo < hi) {
            int mid = (lo + hi) >> 1;
            if (s2c[mid] > thr) hi = mid; else lo = mid + 1;
        }
        g_kofn[bh*NN + n] = lo;
    }
}

// ===================== fused scan + emit (no tables, no RMW) =====================
// Block = (b,h), 512 thr = 8 chunks x 64 o. Counting-sort n by k(n); backward
// E-sweep stashes SufE[k(t)] into smem at emit positions; forward F-sweep emits
// the COMPLETE output with a single coalesced STG. Wh read from L2 (3 passes).
// smem (floats):
#define SM_SUF   0          // 49152  sufE_t[768][64]  (cnt/excl overlay at base)
#define SM_F2S   49152      // 768
#define SM_E2S   49920      // 768
#define SM_PERM  50688      // 768 (int)
#define SM_TL    51456      // 768 (int)
#define SM_KT    52224      // 768 (int)
#define SM_E1T   52992      // 768
#define SM_F1T   53760      // 768
#define SM_IVD   54528      // 768
#define SM_CHF   55296      // 512
#define SM_CHE   55808      // 512
#define SM_TB    56320      // 9 (int)
#define SM_WSS   56336      // 16 (int)
#define ATT2_SMEM ((56352) * 4)
__global__ __launch_bounds__(512)
void attn_emit(const float* __restrict__ Wh, const float* __restrict__ s1,
               float* __restrict__ out) {
    extern __shared__ float sm[];
    float* sufT = sm + SM_SUF;
    float* F2s  = sm + SM_F2S;
    float* E2s  = sm + SM_E2S;
    int*   perm = (int*)(sm + SM_PERM);
    int*   tl   = (int*)(sm + SM_TL);
    int*   kt   = (int*)(sm + SM_KT);
    float* e1t  = sm + SM_E1T;
    float* f1t  = sm + SM_F1T;
    float* ivd  = sm + SM_IVD;
    float* chF  = sm + SM_CHF;
    float* chE  = sm + SM_CHE;
    int*   Tb   = (int*)(sm + SM_TB);
    int*   wsS  = (int*)(sm + SM_WSS);
    int*   cnt  = (int*)(sm + SM_SUF);          // overlay (pre-sweep only)
    int*   excl = (int*)(sm + SM_SUF) + 1024;   // overlay (pre-sweep only)

    const int bh = blockIdx.x, tid = threadIdx.x;
    const int h = bh % NH, b = bh / NH;
    const int c = tid >> 6, o = tid & 63;
    const int lane = tid & 31, wrp = tid >> 5;
    const float* whb = Wh + (size_t)b * NN * FDIM + h * HID + o;

    for (int i = tid; i < 1024; i += 512) cnt[i] = 0;
    for (int i = tid; i < NN; i += 512) {
        F2s[i]  = g_F2s[bh*NN + i];
        E2s[i]  = g_E2s[bh*NN + i];
        perm[i] = g_perm[bh*NN + i];
    }
    __syncthreads();
    for (int n = tid; n < NN; n += 512)
        atomicAdd(&cnt[g_kofn[bh*NN + n]], 1);
    __syncthreads();

    // exclusive scan of cnt[0..1023]
    {
        int i0 = 2*tid, i1 = 2*tid + 1;
        int v0 = cnt[i0], v1 = cnt[i1];
        int ls = v0 + v1, inc = ls;
#pragma unroll
        for (int off = 1; off < 32; off <<= 1) {
            int a = __shfl_up_sync(0xffffffffu, inc, off);
            if (lane >= off) inc += a;
        }
        if (lane == 31) wsS[wrp] = inc;
        __syncthreads();
        if (tid == 0) {
            int a = 0;
            for (int w = 0; w < 16; w++) { a += wsS[w]; wsS[w] = a; }
        }
        __syncthreads();
        int basep = (wrp > 0) ? wsS[wrp-1] : 0;
        int ex = basep + inc - ls;
        excl[i0] = ex; excl[i1] = ex + v0;
    }
    __syncthreads();
    if (tid < 8) Tb[tid] = excl[tid * CH];
    if (tid == 8) Tb[8] = NN;
    __syncthreads();
    // scatter (destroys excl)
    for (int n = tid; n < NN; n += 512) {
        int k = g_kofn[bh*NN + n];
        int pos = atomicAdd(&excl[k], 1);
        tl[pos] = n; kt[pos] = k;
    }
    __syncthreads();

    // per-t E1/F1/invden
    float mx = g_s2max[bh];
    const float* pf2 = g_preF2 + bh*(NN+1);
    const float* se2 = g_sufE2 + bh*(NN+1);
    for (int t = tid; t < NN; t += 512) {
        int n = tl[t], k = kt[t];
        float s1v = s1[bh*NN + n];
        float u = s1v + mx;
        float rm = u > 0.f ? u : 0.2f * u;
        float E1 = expf(u - rm), F1 = expf(0.2f * u - rm);
        e1t[t] = E1; f1t[t] = F1;
        ivd[t] = 1.f / (E1 * se2[k] + F1 * pf2[k]);
    }

    // chunk sums (W pass 1)
    float cF = 0.f, cE = 0.f;
#pragma unroll 4
    for (int j = 0; j < CH; j++) {
        int i = c*CH + j;
        float w = whb[(size_t)perm[i] * FDIM];
        cF += F2s[i] * w;
        cE += E2s[i] * w;
    }
    chF[c*HID + o] = cF;
    chE[c*HID + o] = cE;
    __syncthreads();   // also orders scatter/e1t/f1t/ivd before sweeps + frees cnt/excl overlay

    float accF = 0.f, accE = 0.f;
    for (int c2 = 0; c2 < c; c2++)       accF += chF[c2*HID + o];
    for (int c2 = c + 1; c2 < NCH; c2++) accE += chE[c2*HID + o];
    const int tlo = Tb[c], thi = Tb[c+1];

    // backward E-sweep (W pass 2): stash SufE[k(t)] into smem at emit positions
    {
        int t = thi - 1;
#pragma unroll 4
        for (int j = CH - 1; j >= 0; j--) {
            int i = c*CH + j;
            while (t >= tlo && kt[t] == i + 1) {
                sufT[t*HID + o] = accE;
                t--;
            }
            accE += E2s[i] * whb[(size_t)perm[i] * FDIM];
        }
        while (t >= tlo) {       // kt == c*CH
            sufT[t*HID + o] = accE;
            t--;
        }
    }
    // forward F-sweep (W pass 3): emit complete output, single STG, no RMW
    {
        int t = tlo;
#pragma unroll 4
        for (int j = 0; j < CH; j++) {
            int i = c*CH + j;
            while (t < thi && kt[t] == i) {
                int n = tl[t];
                out[((size_t)(b*NN + n))*FDIM + h*HID + o] =
                    (f1t[t] * accF + e1t[t] * sufT[t*HID + o]) * ivd[t];
                t++;
            }
            accF += F2s[i] * whb[(size_t)perm[i] * FDIM];
        }
        while (t < thi) {        // kt == NN (chunk 7 tail): SufE = 0 already stashed
            int n = tl[t];
            out[((size_t)(b*NN + n))*FDIM + h*HID + o] =
                (f1t[t] * accF + e1t[t] * sufT[t*HID + o]) * ivd[t];
            t++;
        }
    }
}

static void run_gat_layer(const float* hin, const float* Bt, const float* att,
                          float* Wh, float* hout, int K) {
    float *s1, *s2;
    cudaGetSymbolAddress((void**)&s1, g_s1);
    cudaGetSymbolAddress((void**)&s2, g_s2);
    tf32_gemm<<<dim3(BN/128, FDIM/64), 128>>>(hin, Bt, nullptr, Wh, FDIM, K, att, s1, s2);
    sort_prep<<<BH, 512>>>(s2, s1);
    attn_emit<<<BH, 512, ATT2_SMEM>>>(Wh, s1, hout);
}

extern "C" void kernel_launch(void* const* d_in, const int* in_sizes, int n_in,
                              void* d_out, int out_size) {
    const float* x    = (const float*)d_in[0];
    const float* ip_w = (const float*)d_in[1];
    const float* ip_b = (const float*)d_in[2];
    const float* w0   = (const float*)d_in[3];
    const float* a0   = (const float*)d_in[4];
    const float* w1   = (const float*)d_in[5];
    const float* a1   = (const float*)d_in[6];
    const float* pw   = (const float*)d_in[7];
    const float* pb   = (const float*)d_in[8];
    float* out = (float*)d_out;

    cudaFuncSetAttribute(attn_emit, cudaFuncAttributeMaxDynamicSharedMemorySize, ATT2_SMEM);

    float *h0, *Wh, *hc1, *hc2, *B0t, *B1t, *pwT;
    cudaGetSymbolAddress((void**)&h0,  g_h0);
    cudaGetSymbolAddress((void**)&Wh,  g_Wh);
    cudaGetSymbolAddress((void**)&hc1, g_hc1);
    cudaGetSymbolAddress((void**)&hc2, g_hc2);
    cudaGetSymbolAddress((void**)&B0t, g_B0t);
    cudaGetSymbolAddress((void**)&B1t, g_B1t);
    cudaGetSymbolAddress((void**)&pwT, g_pwT);

    prep_B<<<512, 256>>>(w0, w1, pw);

    // input projection: h0 = x @ ip_w + ip_b
    sgemm<<<dim3(BN/64, HID/64), 256>>>(x, ip_w, ip_b, h0, BN, HID, INDIM);

    run_gat_layer(h0,  B0t, a0, Wh, hc1, HID);   // GAT layer 0
    run_gat_layer(hc1, B1t, a1, Wh, hc2, FDIM);  // GAT layer 1

    // output projection
    tf32_gemm<<<dim3(BN/128, EMB/64), 128>>>(hc2, pwT, pb, out, EMB, FDIM,
                                             nullptr, nullptr, nullptr);
}

// round 11
// speedup vs baseline: 1.4102x; 1.4102x over previous
#include <cuda_runtime.h>
#include <math.h>
#include <stdint.h>

#define BSZ 16
#define NN 768
#define INDIM 16
#define HID 64
#define EMB 128
#define NH 8
#define BN (BSZ*NN)        // 12288
#define FDIM (NH*HID)      // 512
#define BH (BSZ*NH)        // 128
#define BHN (BH*NN)        // 98304
#define CH 96
#define NCH 8              // CH*NCH = 768

// ---- static scratch ----
__device__ float g_h0 [BN*HID];
__device__ float g_Wh [BN*FDIM];
__device__ float g_hc1[BN*FDIM];
__device__ float g_hc2[BN*FDIM];
__device__ float g_s1[BHN], g_s2[BHN];
__device__ int   g_kofn[BHN];
__device__ float g_s2max[BH];
__device__ float g_preF2[BH*(NN+1)], g_sufE2[BH*(NN+1)];
__device__ float g_PreF[(size_t)BH*(NN+1)*HID];
__device__ float g_SufE[(size_t)BH*(NN+1)*HID];
__device__ float g_B0t[FDIM*HID];
__device__ float g_B1t[FDIM*FDIM];
__device__ float g_pwT[EMB*FDIM];

// ===================== HMMA tf32 GEMM (+ fused score) =====================
__device__ __forceinline__ uint32_t smem_u32(const void* p) {
    uint32_t a;
    asm("{ .reg .u64 t; cvta.to.shared.u64 t, %1; cvt.u32.u64 %0, t; }" : "=r"(a) : "l"(p));
    return a;
}
__device__ __forceinline__ uint32_t f2tf(float x) {
    uint32_t u; asm("cvt.rna.tf32.f32 %0, %1;" : "=r"(u) : "f"(x)); return u;
}
__device__ __forceinline__ void mma_tf32(float* d, const uint32_t* a, const uint32_t* b) {
    asm volatile("mma.sync.aligned.m16n8k8.row.col.f32.tf32.tf32.f32 "
                 "{%0,%1,%2,%3}, {%4,%5,%6,%7}, {%8,%9}, {%0,%1,%2,%3};"
                 : "+f"(d[0]), "+f"(d[1]), "+f"(d[2]), "+f"(d[3])
                 : "r"(a[0]), "r"(a[1]), "r"(a[2]), "r"(a[3]), "r"(b[0]), "r"(b[1]));
}
#define CP16(dst, src) \
    asm volatile("cp.async.ca.shared.global [%0], [%1], 16;" :: "r"(dst), "l"(src) : "memory")
#define CP_COMMIT()  asm volatile("cp.async.commit_group;" ::: "memory")
#define CP_WAIT0()   asm volatile("cp.async.wait_group 0;" ::: "memory")

__device__ __forceinline__ int swz(int row, int k) {
    return row * 32 + ((((k >> 2) ^ (row & 7)) << 2) | (k & 3));
}

__global__ __launch_bounds__(128)
void tf32_gemm(const float* __restrict__ A, const float* __restrict__ Bt,
               const float* __restrict__ bias, float* __restrict__ C,
               int N, int K,
               const float* __restrict__ att, float* __restrict__ s1out,
               float* __restrict__ s2out) {
    __shared__ float As[2][128 * 32];
    __shared__ float Bs[2][64 * 32];
    __shared__ float sp1[128], sp2[128];
    const int tid = threadIdx.x;
    const int wid = tid >> 5, lane = tid & 31;
    const int r = lane >> 2, cc = lane & 3;
    const int warp_m = (wid & 1) * 64, warp_n = (wid >> 1) * 32;
    const int m0 = blockIdx.x * 128, n0 = blockIdx.y * 64;

    sp1[tid] = 0.f; sp2[tid] = 0.f;

    uint32_t asb[2] = { smem_u32(&As[0][0]), smem_u32(&As[1][0]) };
    uint32_t bsb[2] = { smem_u32(&Bs[0][0]), smem_u32(&Bs[1][0]) };

    float acc[4][4][4] = {};
    const int NC = K >> 5;

    {
#pragma unroll
        for (int j = 0; j < 8; j++) {
            int u = tid + j * 128, row = u >> 3, ch = u & 7;
            CP16(asb[0] + (uint32_t)(row * 32 + ((ch ^ (row & 7)) << 2)) * 4,
                 A + (size_t)(m0 + row) * K + ch * 4);
        }
#pragma unroll
        for (int j = 0; j < 4; j++) {
            int u = tid + j * 128, row = u >> 3, ch = u & 7;
            CP16(bsb[0] + (uint32_t)(row * 32 + ((ch ^ (row & 7)) << 2)) * 4,
                 Bt + (size_t)(n0 + row) * K + ch * 4);
        }
        CP_COMMIT();
    }

    for (int i = 0; i < NC; i++) {
        CP_WAIT0();
        __syncthreads();
        if (i + 1 < NC) {
            int nb = (i + 1) & 1, kc = (i + 1) * 32;
#pragma unroll
            for (int j = 0; j < 8; j++) {
                int u = tid + j * 128, row = u >> 3, ch = u & 7;
                CP16(asb[nb] + (uint32_t)(row * 32 + ((ch ^ (row & 7)) << 2)) * 4,
                     A + (size_t)(m0 + row) * K + kc + ch * 4);
            }
#pragma unroll
            for (int j = 0; j < 4; j++) {
                int u = tid + j * 128, row = u >> 3, ch = u & 7;
                CP16(bsb[nb] + (uint32_t)(row * 32 + ((ch ^ (row & 7)) << 2)) * 4,
                     Bt + (size_t)(n0 + row) * K + kc + ch * 4);
            }
            CP_COMMIT();
        }
        const float* as = As[i & 1];
        const float* bs = Bs[i & 1];
#pragma unroll
        for (int ks = 0; ks < 4; ks++) {
            uint32_t af[4][4], bf[4][2];
#pragma unroll
            for (int mt = 0; mt < 4; mt++) {
                int rb = warp_m + mt * 16 + r;
                af[mt][0] = f2tf(as[swz(rb,     ks * 8 + cc)]);
                af[mt][1] = f2tf(as[swz(rb + 8, ks * 8 + cc)]);
                af[mt][2] = f2tf(as[swz(rb,     ks * 8 + cc + 4)]);
                af[mt][3] = f2tf(as[swz(rb + 8, ks * 8 + cc + 4)]);
            }
#pragma unroll
            for (int nt = 0; nt < 4; nt++) {
                int nb = warp_n + nt * 8 + r;
                bf[nt][0] = f2tf(bs[swz(nb, ks * 8 + cc)]);
                bf[nt][1] = f2tf(bs[swz(nb, ks * 8 + cc + 4)]);
            }
#pragma unroll
            for (int mt = 0; mt < 4; mt++)
#pragma unroll
                for (int nt = 0; nt < 4; nt++)
                    mma_tf32(acc[mt][nt], af[mt], bf[nt]);
        }
        __syncthreads();
    }

#pragma unroll
    for (int mt = 0; mt < 4; mt++) {
#pragma unroll
        for (int nt = 0; nt < 4; nt++) {
            int row = m0 + warp_m + mt * 16 + r;
            int col = n0 + warp_n + nt * 8 + cc * 2;
            float bx = 0.f, by = 0.f;
            if (bias) { bx = bias[col]; by = bias[col + 1]; }
            float2 v0 = { acc[mt][nt][0] + bx, acc[mt][nt][1] + by };
            float2 v1 = { acc[mt][nt][2] + bx, acc[mt][nt][3] + by };
            *(float2*)&C[(size_t)row * N + col] = v0;
            *(float2*)&C[(size_t)(row + 8) * N + col] = v1;
        }
    }

    if (att) {
        int h = n0 >> 6;
        const float* a1 = att + h * 2 * HID;
        const float* a2 = a1 + HID;
#pragma unroll
        for (int mt = 0; mt < 4; mt++) {
            float p1a = 0.f, p2a = 0.f, p1b = 0.f, p2b = 0.f;
#pragma unroll
            for (int nt = 0; nt < 4; nt++) {
                int col = warp_n + nt * 8 + cc * 2;
                float a1x = a1[col], a1y = a1[col + 1];
                float a2x = a2[col], a2y = a2[col + 1];
                p1a += acc[mt][nt][0] * a1x + acc[mt][nt][1] * a1y;
                p2a += acc[mt][nt][0] * a2x + acc[mt][nt][1] * a2y;
                p1b += acc[mt][nt][2] * a1x + acc[mt][nt][3] * a1y;
                p2b += acc[mt][nt][2] * a2x + acc[mt][nt][3] * a2y;
            }
#pragma unroll
            for (int off = 1; off <= 2; off <<= 1) {
                p1a += __shfl_xor_sync(0xffffffffu, p1a, off);
                p2a += __shfl_xor_sync(0xffffffffu, p2a, off);
                p1b += __shfl_xor_sync(0xffffffffu, p1b, off);
                p2b += __shfl_xor_sync(0xffffffffu, p2b, off);
            }
            if (cc == 0) {
                int lr = warp_m + mt * 16 + r;
                atomicAdd(&sp1[lr], p1a);     atomicAdd(&sp2[lr], p2a);
                atomicAdd(&sp1[lr + 8], p1b); atomicAdd(&sp2[lr + 8], p2b);
            }
        }
        __syncthreads();
        int gr = m0 + tid;
        int b2 = gr / NN, n2 = gr % NN;
        int bh2 = b2 * NH + h;
        s1out[bh2 * NN + n2] = sp1[tid];
        s2out[bh2 * NN + n2] = sp2[tid];
    }
}

// ===================== non-GEMM kernels =====================

__global__ void prep_B(const float* __restrict__ w0, const float* __restrict__ w1,
                       const float* __restrict__ pw) {
    int i0 = blockIdx.x * blockDim.x + threadIdx.x;
    int stride = gridDim.x * blockDim.x;
    for (int i = i0; i < FDIM*HID; i += stride) {
        int n = i / HID, f = i % HID;
        g_B0t[i] = w0[(n / HID) * (HID*HID) + f * HID + (n % HID)];
    }
    for (int i = i0; i < FDIM*FDIM; i += stride) {
        int n = i / FDIM, f = i % FDIM;
        g_B1t[i] = w1[(n / HID) * (FDIM*HID) + f * HID + (n % HID)];
    }
    for (int i = i0; i < EMB*FDIM; i += stride) {
        int n = i / FDIM, k = i % FDIM;
        g_pwT[i] = pw[k * EMB + n];
    }
}

// small fp32 SGEMM for the input projection (K=16)
__global__ void sgemm(const float* __restrict__ A, const float* __restrict__ B,
                      const float* __restrict__ bias, float* __restrict__ C,
                      int M, int N, int K) {
    __shared__ float As[16][64];
    __shared__ float Bs[16][64];
    int tid = threadIdx.x;
    int m0 = blockIdx.x * 64, n0 = blockIdx.y * 64;
    int tx = tid & 15, ty = tid >> 4;
    int arow = tid >> 2, acol = (tid & 3) * 4;
    int brow = tid >> 4, bcol = (tid & 15) * 4;
    float acc[4][4] = {};
    for (int kc = 0; kc < K; kc += 16) {
        float4 av = *(const float4*)&A[(size_t)(m0 + arow) * K + kc + acol];
        As[acol+0][arow] = av.x; As[acol+1][arow] = av.y;
        As[acol+2][arow] = av.z; As[acol+3][arow] = av.w;
        *(float4*)&Bs[brow][bcol] = *(const float4*)&B[(size_t)(kc + brow) * N + n0 + bcol];
        __syncthreads();
#pragma unroll
        for (int k = 0; k < 16; k++) {
            float4 a4 = *(float4*)&As[k][ty*4];
            float4 b4 = *(float4*)&Bs[k][tx*4];
            float a[4] = {a4.x, a4.y, a4.z, a4.w};
            float b[4] = {b4.x, b4.y, b4.z, b4.w};
#pragma unroll
            for (int i = 0; i < 4; i++)
#pragma unroll
                for (int j = 0; j < 4; j++) acc[i][j] += a[i] * b[j];
        }
        __syncthreads();
    }
#pragma unroll
    for (int i = 0; i < 4; i++) {
        int m = m0 + ty*4 + i, n = n0 + tx*4;
        float4 v = {acc[i][0], acc[i][1], acc[i][2], acc[i][3]};
        if (bias) { v.x += bias[n]; v.y += bias[n+1]; v.z += bias[n+2]; v.w += bias[n+3]; }
        *(float4*)&C[(size_t)m * N + n] = v;
    }
}

// Fused: per (b,h) u64-bitonic sort of s2 + E2/F2 + scalar scans + k(n),
// then chunk sums + PreF/SufE table write (scan phase reads fe/ff/perm from smem).
// 512 threads; scan phase uses 8 chunks x 64 o-lanes. ~25KB static smem.
__global__ __launch_bounds__(512)
void prep_scan(const float* __restrict__ s2, const float* __restrict__ s1,
               const float* __restrict__ Wh) {
    __shared__ unsigned long long sv[1024];
    __shared__ float fe[NN], ff[NN], s2c[NN];
    __shared__ int   perm[NN];
    __shared__ float wsE[16], wsF[16];
    __shared__ float chF[NCH*HID], chE[NCH*HID];
    const int bh = blockIdx.x, tid = threadIdx.x;
    const int lane = tid & 31, wrp = tid >> 5;
    const int h = bh % NH, b = bh / NH;

    // ---- phase A: sort (identical to R9 sort_prep) ----
    for (int i = tid; i < 1024; i += 512) {
        if (i < NN) {
            uint32_t bt = __float_as_uint(s2[bh*NN + i]);
            uint32_t key = (bt & 0x80000000u) ? ~bt : (bt | 0x80000000u);
            sv[i] = ((unsigned long long)key << 32) | (unsigned)i;
        } else sv[i] = 0xFFFFFFFFFFFFFFFFull;
    }
    __syncthreads();
    for (int k = 2; k <= 1024; k <<= 1) {
        for (int j = k >> 1; j > 0; j >>= 1) {
            for (int i = tid; i < 1024; i += 512) {
                int ixj = i ^ j;
                if (ixj > i) {
                    bool up = ((i & k) == 0);
                    unsigned long long a = sv[i], bb = sv[ixj];
                    if ((a > bb) == up) { sv[i] = bb; sv[ixj] = a; }
                }
            }
            __syncthreads();
        }
    }
    float mx;
    {
        uint32_t keyN = (uint32_t)(sv[NN-1] >> 32);
        uint32_t bt = (keyN & 0x80000000u) ? (keyN & 0x7FFFFFFFu) : ~keyN;
        mx = __uint_as_float(bt);
    }
    if (tid == 0) g_s2max[bh] = mx;
    for (int i = tid; i < NN; i += 512) {
        unsigned long long p = sv[i];
        uint32_t key = (uint32_t)(p >> 32);
        uint32_t bt = (key & 0x80000000u) ? (key & 0x7FFFFFFFu) : ~key;
        float v = __uint_as_float(bt);
        float d = v - mx;
        float e = expf(d), f = expf(0.2f * d);
        fe[i] = e; ff[i] = f;
        s2c[i] = v;
        perm[i] = (int)(p & 0xFFFFFFFFu);
    }
    __syncthreads();

    // scalar scans (thread owns elems 2t, 2t+1)
    {
        int i0 = 2 * tid, i1 = 2 * tid + 1;
        float e0 = (i0 < NN) ? fe[i0] : 0.f, e1 = (i1 < NN) ? fe[i1] : 0.f;
        float f0 = (i0 < NN) ? ff[i0] : 0.f, f1 = (i1 < NN) ? ff[i1] : 0.f;
        float le = e0 + e1, lf = f0 + f1;
        float eI = le, fI = lf;
#pragma unroll
        for (int off = 1; off < 32; off <<= 1) {
            float a = __shfl_up_sync(0xffffffffu, eI, off);
            float bb = __shfl_up_sync(0xffffffffu, fI, off);
            if (lane >= off) { eI += a; fI += bb; }
        }
        if (lane == 31) { wsE[wrp] = eI; wsF[wrp] = fI; }
        __syncthreads();
        if (tid == 0) {
            float a = 0.f, bb = 0.f;
            for (int w = 0; w < 16; w++) { a += wsE[w]; wsE[w] = a; bb += wsF[w]; wsF[w] = bb; }
        }
        __syncthreads();
        float baseE = (wrp > 0) ? wsE[wrp-1] : 0.f;
        float baseF = (wrp > 0) ? wsF[wrp-1] : 0.f;
        float eexcl = baseE + (eI - le);
        float fexcl = baseF + (fI - lf);
        float totE = wsE[15], totF = wsF[15];
        int base = bh * (NN + 1);
        if (i0 < NN) { g_preF2[base + i0] = fexcl;      g_sufE2[base + i0] = totE - eexcl; }
        if (i1 < NN) { g_preF2[base + i1] = fexcl + f0; g_sufE2[base + i1] = totE - (eexcl + e0); }
        if (tid == 0) { g_preF2[base + NN] = totF; g_sufE2[base + NN] = 0.f; }
    }

    // k(n) via binary search over sorted s2
    for (int n = tid; n < NN; n += 512) {
        float thr = -s1[bh*NN + n];
        int lo = 0, hi = NN;
        while (lo < hi) {
            int mid = (lo + hi) >> 1;
            if (s2c[mid] > thr) hi = mid; else lo = mid + 1;
        }
        g_kofn[bh*NN + n] = lo;
    }
    __syncthreads();

    // ---- phase B: chunk sums + table write (identical to R9 scan_fused,
    //      but fe/ff/perm come straight from smem) ----
    const int c = tid >> 6, o = tid & 63;
    const float* whb = Wh + (size_t)b * NN * FDIM + h * HID + o;

    float cF = 0.f, cE = 0.f;
#pragma unroll 4
    for (int j = 0; j < CH; j++) {
        int i = c*CH + j;
        float w = whb[(size_t)perm[i] * FDIM];
        cF += ff[i] * w;
        cE += fe[i] * w;
    }
    chF[c*HID + o] = cF;
    chE[c*HID + o] = cE;
    __syncthreads();

    float accF = 0.f, accE = 0.f;
    for (int c2 = 0; c2 < c; c2++)       accF += chF[c2*HID + o];
    for (int c2 = c + 1; c2 < NCH; c2++) accE += chE[c2*HID + o];

    size_t base2 = ((size_t)bh*(NN+1))*HID + o;
#pragma unroll 4
    for (int j = 0; j < CH; j++) {
        int i = c*CH + j;
        float w = whb[(size_t)perm[i] * FDIM];
        g_PreF[base2 + (size_t)i*HID] = accF;
        accF += ff[i] * w;
    }
    if (c == NCH - 1) {
        g_PreF[base2 + (size_t)NN*HID] = accF;
        g_SufE[base2 + (size_t)NN*HID] = 0.f;
    }
#pragma unroll 4
    for (int j = CH - 1; j >= 0; j--) {
        int i = c*CH + j;
        float w = whb[(size_t)perm[i] * FDIM];
        accE += fe[i] * w;
        g_SufE[base2 + (size_t)i*HID] = accE;
    }
}

__global__ void apply_attn(const float* __restrict__ s1, float* __restrict__ out) {
    int bh = blockIdx.y, h = bh % NH, b = bh / NH;
    int n = blockIdx.x * 4 + (threadIdx.x >> 6);
    int o = threadIdx.x & 63;
    float s1v = s1[bh*NN + n];
    float mx = g_s2max[bh];
    float u = s1v + mx;
    float rmax = u > 0.f ? u : 0.2f * u;
    float E1 = expf(u - rmax);
    float F1 = expf(0.2f * u - rmax);
    int k = g_kofn[bh*NN + n];
    size_t idx = ((size_t)bh*(NN+1) + k)*HID + o;
    float num = E1 * g_SufE[idx] + F1 * g_PreF[idx];
    float den = E1 * g_sufE2[bh*(NN+1) + k] + F1 * g_preF2[bh*(NN+1) + k];
    out[((size_t)(b*NN + n))*FDIM + h*HID + o] = num / den;
}

static void run_gat_layer(const float* hin, const float* Bt, const float* att,
                          float* Wh, float* hout, int K) {
    float *s1, *s2;
    cudaGetSymbolAddress((void**)&s1, g_s1);
    cudaGetSymbolAddress((void**)&s2, g_s2);
    tf32_gemm<<<dim3(BN/128, FDIM/64), 128>>>(hin, Bt, nullptr, Wh, FDIM, K, att, s1, s2);
    prep_scan<<<BH, 512>>>(s2, s1, Wh);
    apply_attn<<<dim3(NN/4, BH), 256>>>(s1, hout);
}

extern "C" void kernel_launch(void* const* d_in, const int* in_sizes, int n_in,
                              void* d_out, int out_size) {
    const float* x    = (const float*)d_in[0];
    const float* ip_w = (const float*)d_in[1];
    const float* ip_b = (const float*)d_in[2];
    const float* w0   = (const float*)d_in[3];
    const float* a0   = (const float*)d_in[4];
    const float* w1   = (const float*)d_in[5];
    const float* a1   = (const float*)d_in[6];
    const float* pw   = (const float*)d_in[7];
    const float* pb   = (const float*)d_in[8];
    float* out = (float*)d_out;

    float *h0, *Wh, *hc1, *hc2, *B0t, *B1t, *pwT;
    cudaGetSymbolAddress((void**)&h0,  g_h0);
    cudaGetSymbolAddress((void**)&Wh,  g_Wh);
    cudaGetSymbolAddress((void**)&hc1, g_hc1);
    cudaGetSymbolAddress((void**)&hc2, g_hc2);
    cudaGetSymbolAddress((void**)&B0t, g_B0t);
    cudaGetSymbolAddress((void**)&B1t, g_B1t);
    cudaGetSymbolAddress((void**)&pwT, g_pwT);

    prep_B<<<512, 256>>>(w0, w1, pw);

    // input projection: h0 = x @ ip_w + ip_b
    sgemm<<<dim3(BN/64, HID/64), 256>>>(x, ip_w, ip_b, h0, BN, HID, INDIM);

    run_gat_layer(h0,  B0t, a0, Wh, hc1, HID);   // GAT layer 0
    run_gat_layer(hc1, B1t, a1, Wh, hc2, FDIM);  // GAT layer 1

    // output projection
    tf32_gemm<<<dim3(BN/128, EMB/64), 128>>>(hc2, pwT, pb, out, EMB, FDIM,
                                             nullptr, nullptr, nullptr);
}

// round 12
// speedup vs baseline: 1.5020x; 1.0651x over previous
#include <cuda_runtime.h>
#include <math.h>
#include <stdint.h>

#define BSZ 16
#define NN 768
#define INDIM 16
#define HID 64
#define EMB 128
#define NH 8
#define BN (BSZ*NN)        // 12288
#define FDIM (NH*HID)      // 512
#define BH (BSZ*NH)        // 128
#define BHN (BH*NN)        // 98304
#define CH 96
#define NCH 8              // CH*NCH = 768

// ---- static scratch ----
__device__ float g_h0 [BN*HID];
__device__ float g_Wh [BN*FDIM];
__device__ float g_hc1[BN*FDIM];
__device__ float g_hc2[BN*FDIM];
__device__ float g_s1[BHN], g_s2[BHN];
__device__ int   g_kofn[BHN];
__device__ float g_s2max[BH];
__device__ float g_preF2[BH*(NN+1)], g_sufE2[BH*(NN+1)];
__device__ float g_PreF[(size_t)BH*(NN+1)*HID];
__device__ float g_SufE[(size_t)BH*(NN+1)*HID];
__device__ float g_B0t[FDIM*HID];
__device__ float g_B1t[FDIM*FDIM];
__device__ float g_pwT[EMB*FDIM];

// ===================== HMMA tf32 GEMM (+ fused score) =====================
__device__ __forceinline__ uint32_t smem_u32(const void* p) {
    uint32_t a;
    asm("{ .reg .u64 t; cvta.to.shared.u64 t, %1; cvt.u32.u64 %0, t; }" : "=r"(a) : "l"(p));
    return a;
}
__device__ __forceinline__ uint32_t f2tf(float x) {
    uint32_t u; asm("cvt.rna.tf32.f32 %0, %1;" : "=r"(u) : "f"(x)); return u;
}
__device__ __forceinline__ float rnd_tf32(float x) {       // round-at-producer
    return __uint_as_float(f2tf(x));
}
__device__ __forceinline__ void mma_tf32(float* d, const uint32_t* a, const uint32_t* b) {
    asm volatile("mma.sync.aligned.m16n8k8.row.col.f32.tf32.tf32.f32 "
                 "{%0,%1,%2,%3}, {%4,%5,%6,%7}, {%8,%9}, {%0,%1,%2,%3};"
                 : "+f"(d[0]), "+f"(d[1]), "+f"(d[2]), "+f"(d[3])
                 : "r"(a[0]), "r"(a[1]), "r"(a[2]), "r"(a[3]), "r"(b[0]), "r"(b[1]));
}
#define CP16(dst, src) \
    asm volatile("cp.async.ca.shared.global [%0], [%1], 16;" :: "r"(dst), "l"(src) : "memory")
#define CP_COMMIT()  asm volatile("cp.async.commit_group;" ::: "memory")
#define CP_WAIT0()   asm volatile("cp.async.wait_group 0;" ::: "memory")

__device__ __forceinline__ int swz(int row, int k) {
    return row * 32 + ((((k >> 2) ^ (row & 7)) << 2) | (k & 3));
}

// Operands are PRE-ROUNDED tf32 bit patterns: inner loop is pure LDS.u32 + MMA.
__global__ __launch_bounds__(128)
void tf32_gemm(const float* __restrict__ A, const float* __restrict__ Bt,
               const float* __restrict__ bias, float* __restrict__ C,
               int N, int K,
               const float* __restrict__ att, float* __restrict__ s1out,
               float* __restrict__ s2out) {
    __shared__ float As[2][128 * 32];
    __shared__ float Bs[2][64 * 32];
    __shared__ float sp1[128], sp2[128];
    const int tid = threadIdx.x;
    const int wid = tid >> 5, lane = tid & 31;
    const int r = lane >> 2, cc = lane & 3;
    const int warp_m = (wid & 1) * 64, warp_n = (wid >> 1) * 32;
    const int m0 = blockIdx.x * 128, n0 = blockIdx.y * 64;

    sp1[tid] = 0.f; sp2[tid] = 0.f;

    uint32_t asb[2] = { smem_u32(&As[0][0]), smem_u32(&As[1][0]) };
    uint32_t bsb[2] = { smem_u32(&Bs[0][0]), smem_u32(&Bs[1][0]) };

    float acc[4][4][4] = {};
    const int NC = K >> 5;

    {
#pragma unroll
        for (int j = 0; j < 8; j++) {
            int u = tid + j * 128, row = u >> 3, ch = u & 7;
            CP16(asb[0] + (uint32_t)(row * 32 + ((ch ^ (row & 7)) << 2)) * 4,
                 A + (size_t)(m0 + row) * K + ch * 4);
        }
#pragma unroll
        for (int j = 0; j < 4; j++) {
            int u = tid + j * 128, row = u >> 3, ch = u & 7;
            CP16(bsb[0] + (uint32_t)(row * 32 + ((ch ^ (row & 7)) << 2)) * 4,
                 Bt + (size_t)(n0 + row) * K + ch * 4);
        }
        CP_COMMIT();
    }

    for (int i = 0; i < NC; i++) {
        CP_WAIT0();
        __syncthreads();
        if (i + 1 < NC) {
            int nb = (i + 1) & 1, kc = (i + 1) * 32;
#pragma unroll
            for (int j = 0; j < 8; j++) {
                int u = tid + j * 128, row = u >> 3, ch = u & 7;
                CP16(asb[nb] + (uint32_t)(row * 32 + ((ch ^ (row & 7)) << 2)) * 4,
                     A + (size_t)(m0 + row) * K + kc + ch * 4);
            }
#pragma unroll
            for (int j = 0; j < 4; j++) {
                int u = tid + j * 128, row = u >> 3, ch = u & 7;
                CP16(bsb[nb] + (uint32_t)(row * 32 + ((ch ^ (row & 7)) << 2)) * 4,
                     Bt + (size_t)(n0 + row) * K + kc + ch * 4);
            }
            CP_COMMIT();
        }
        const uint32_t* as = (const uint32_t*)As[i & 1];
        const uint32_t* bs = (const uint32_t*)Bs[i & 1];
#pragma unroll
        for (int ks = 0; ks < 4; ks++) {
            uint32_t af[4][4], bf[4][2];
#pragma unroll
            for (int mt = 0; mt < 4; mt++) {
                int rb = warp_m + mt * 16 + r;
                af[mt][0] = as[swz(rb,     ks * 8 + cc)];
                af[mt][1] = as[swz(rb + 8, ks * 8 + cc)];
                af[mt][2] = as[swz(rb,     ks * 8 + cc + 4)];
                af[mt][3] = as[swz(rb + 8, ks * 8 + cc + 4)];
            }
#pragma unroll
            for (int nt = 0; nt < 4; nt++) {
                int nb = warp_n + nt * 8 + r;
                bf[nt][0] = bs[swz(nb, ks * 8 + cc)];
                bf[nt][1] = bs[swz(nb, ks * 8 + cc + 4)];
            }
#pragma unroll
            for (int mt = 0; mt < 4; mt++)
#pragma unroll
                for (int nt = 0; nt < 4; nt++)
                    mma_tf32(acc[mt][nt], af[mt], bf[nt]);
        }
        __syncthreads();
    }

#pragma unroll
    for (int mt = 0; mt < 4; mt++) {
#pragma unroll
        for (int nt = 0; nt < 4; nt++) {
            int row = m0 + warp_m + mt * 16 + r;
            int col = n0 + warp_n + nt * 8 + cc * 2;
            float bx = 0.f, by = 0.f;
            if (bias) { bx = bias[col]; by = bias[col + 1]; }
            float2 v0 = { acc[mt][nt][0] + bx, acc[mt][nt][1] + by };
            float2 v1 = { acc[mt][nt][2] + bx, acc[mt][nt][3] + by };
            *(float2*)&C[(size_t)row * N + col] = v0;
            *(float2*)&C[(size_t)(row + 8) * N + col] = v1;
        }
    }

    if (att) {
        int h = n0 >> 6;
        const float* a1 = att + h * 2 * HID;
        const float* a2 = a1 + HID;
#pragma unroll
        for (int mt = 0; mt < 4; mt++) {
            float p1a = 0.f, p2a = 0.f, p1b = 0.f, p2b = 0.f;
#pragma unroll
            for (int nt = 0; nt < 4; nt++) {
                int col = warp_n + nt * 8 + cc * 2;
                float a1x = a1[col], a1y = a1[col + 1];
                float a2x = a2[col], a2y = a2[col + 1];
                p1a += acc[mt][nt][0] * a1x + acc[mt][nt][1] * a1y;
                p2a += acc[mt][nt][0] * a2x + acc[mt][nt][1] * a2y;
                p1b += acc[mt][nt][2] * a1x + acc[mt][nt][3] * a1y;
                p2b += acc[mt][nt][2] * a2x + acc[mt][nt][3] * a2y;
            }
#pragma unroll
            for (int off = 1; off <= 2; off <<= 1) {
                p1a += __shfl_xor_sync(0xffffffffu, p1a, off);
                p2a += __shfl_xor_sync(0xffffffffu, p2a, off);
                p1b += __shfl_xor_sync(0xffffffffu, p1b, off);
                p2b += __shfl_xor_sync(0xffffffffu, p2b, off);
            }
            if (cc == 0) {
                int lr = warp_m + mt * 16 + r;
                atomicAdd(&sp1[lr], p1a);     atomicAdd(&sp2[lr], p2a);
                atomicAdd(&sp1[lr + 8], p1b); atomicAdd(&sp2[lr + 8], p2b);
            }
        }
        __syncthreads();
        int gr = m0 + tid;
        int b2 = gr / NN, n2 = gr % NN;
        int bh2 = b2 * NH + h;
        s1out[bh2 * NN + n2] = sp1[tid];
        s2out[bh2 * NN + n2] = sp2[tid];
    }
}

// ===================== non-GEMM kernels =====================

// Weights stored PRE-ROUNDED to tf32 bit patterns.
__global__ void prep_B(const float* __restrict__ w0, const float* __restrict__ w1,
                       const float* __restrict__ pw) {
    int i0 = blockIdx.x * blockDim.x + threadIdx.x;
    int stride = gridDim.x * blockDim.x;
    for (int i = i0; i < FDIM*HID; i += stride) {
        int n = i / HID, f = i % HID;
        g_B0t[i] = rnd_tf32(w0[(n / HID) * (HID*HID) + f * HID + (n % HID)]);
    }
    for (int i = i0; i < FDIM*FDIM; i += stride) {
        int n = i / FDIM, f = i % FDIM;
        g_B1t[i] = rnd_tf32(w1[(n / HID) * (FDIM*HID) + f * HID + (n % HID)]);
    }
    for (int i = i0; i < EMB*FDIM; i += stride) {
        int n = i / FDIM, k = i % FDIM;
        g_pwT[i] = rnd_tf32(pw[k * EMB + n]);
    }
}

// small fp32 SGEMM for the input projection (K=16); output PRE-ROUNDED (h0
// feeds only the layer-0 tf32 GEMM, which previously rounded it at load).
__global__ void sgemm(const float* __restrict__ A, const float* __restrict__ B,
                      const float* __restrict__ bias, float* __restrict__ C,
                      int M, int N, int K) {
    __shared__ float As[16][64];
    __shared__ float Bs[16][64];
    int tid = threadIdx.x;
    int m0 = blockIdx.x * 64, n0 = blockIdx.y * 64;
    int tx = tid & 15, ty = tid >> 4;
    int arow = tid >> 2, acol = (tid & 3) * 4;
    int brow = tid >> 4, bcol = (tid & 15) * 4;
    float acc[4][4] = {};
    for (int kc = 0; kc < K; kc += 16) {
        float4 av = *(const float4*)&A[(size_t)(m0 + arow) * K + kc + acol];
        As[acol+0][arow] = av.x; As[acol+1][arow] = av.y;
        As[acol+2][arow] = av.z; As[acol+3][arow] = av.w;
        *(float4*)&Bs[brow][bcol] = *(const float4*)&B[(size_t)(kc + brow) * N + n0 + bcol];
        __syncthreads();
#pragma unroll
        for (int k = 0; k < 16; k++) {
            float4 a4 = *(float4*)&As[k][ty*4];
            float4 b4 = *(float4*)&Bs[k][tx*4];
            float a[4] = {a4.x, a4.y, a4.z, a4.w};
            float b[4] = {b4.x, b4.y, b4.z, b4.w};
#pragma unroll
            for (int i = 0; i < 4; i++)
#pragma unroll
                for (int j = 0; j < 4; j++) acc[i][j] += a[i] * b[j];
        }
        __syncthreads();
    }
#pragma unroll
    for (int i = 0; i < 4; i++) {
        int m = m0 + ty*4 + i, n = n0 + tx*4;
        float4 v = {rnd_tf32(acc[i][0] + bias[n]),   rnd_tf32(acc[i][1] + bias[n+1]),
                    rnd_tf32(acc[i][2] + bias[n+2]), rnd_tf32(acc[i][3] + bias[n+3])};
        *(float4*)&C[(size_t)m * N + n] = v;
    }
}

// Fused: per (b,h) u64-bitonic sort of s2 + E2/F2 + scalar scans + k(n),
// then chunk sums + PreF/SufE table write.
__global__ __launch_bounds__(512)
void prep_scan(const float* __restrict__ s2, const float* __restrict__ s1,
               const float* __restrict__ Wh) {
    __shared__ unsigned long long sv[1024];
    __shared__ float fe[NN], ff[NN], s2c[NN];
    __shared__ int   perm[NN];
    __shared__ float wsE[16], wsF[16];
    __shared__ float chF[NCH*HID], chE[NCH*HID];
    const int bh = blockIdx.x, tid = threadIdx.x;
    const int lane = tid & 31, wrp = tid >> 5;
    const int h = bh % NH, b = bh / NH;

    for (int i = tid; i < 1024; i += 512) {
        if (i < NN) {
            uint32_t bt = __float_as_uint(s2[bh*NN + i]);
            uint32_t key = (bt & 0x80000000u) ? ~bt : (bt | 0x80000000u);
            sv[i] = ((unsigned long long)key << 32) | (unsigned)i;
        } else sv[i] = 0xFFFFFFFFFFFFFFFFull;
    }
    __syncthreads();
    for (int k = 2; k <= 1024; k <<= 1) {
        for (int j = k >> 1; j > 0; j >>= 1) {
            for (int i = tid; i < 1024; i += 512) {
                int ixj = i ^ j;
                if (ixj > i) {
                    bool up = ((i & k) == 0);
                    unsigned long long a = sv[i], bb = sv[ixj];
                    if ((a > bb) == up) { sv[i] = bb; sv[ixj] = a; }
                }
            }
            __syncthreads();
        }
    }
    float mx;
    {
        uint32_t keyN = (uint32_t)(sv[NN-1] >> 32);
        uint32_t bt = (keyN & 0x80000000u) ? (keyN & 0x7FFFFFFFu) : ~keyN;
        mx = __uint_as_float(bt);
    }
    if (tid == 0) g_s2max[bh] = mx;
    for (int i = tid; i < NN; i += 512) {
        unsigned long long p = sv[i];
        uint32_t key = (uint32_t)(p >> 32);
        uint32_t bt = (key & 0x80000000u) ? (key & 0x7FFFFFFFu) : ~key;
        float v = __uint_as_float(bt);
        float d = v - mx;
        float e = expf(d), f = expf(0.2f * d);
        fe[i] = e; ff[i] = f;
        s2c[i] = v;
        perm[i] = (int)(p & 0xFFFFFFFFu);
    }
    __syncthreads();

    {
        int i0 = 2 * tid, i1 = 2 * tid + 1;
        float e0 = (i0 < NN) ? fe[i0] : 0.f, e1 = (i1 < NN) ? fe[i1] : 0.f;
        float f0 = (i0 < NN) ? ff[i0] : 0.f, f1 = (i1 < NN) ? ff[i1] : 0.f;
        float le = e0 + e1, lf = f0 + f1;
        float eI = le, fI = lf;
#pragma unroll
        for (int off = 1; off < 32; off <<= 1) {
            float a = __shfl_up_sync(0xffffffffu, eI, off);
            float bb = __shfl_up_sync(0xffffffffu, fI, off);
            if (lane >= off) { eI += a; fI += bb; }
        }
        if (lane == 31) { wsE[wrp] = eI; wsF[wrp] = fI; }
        __syncthreads();
        if (tid == 0) {
            float a = 0.f, bb = 0.f;
            for (int w = 0; w < 16; w++) { a += wsE[w]; wsE[w] = a; bb += wsF[w]; wsF[w] = bb; }
        }
        __syncthreads();
        float baseE = (wrp > 0) ? wsE[wrp-1] : 0.f;
        float baseF = (wrp > 0) ? wsF[wrp-1] : 0.f;
        float eexcl = baseE + (eI - le);
        float fexcl = baseF + (fI - lf);
        float totE = wsE[15], totF = wsF[15];
        int base = bh * (NN + 1);
        if (i0 < NN) { g_preF2[base + i0] = fexcl;      g_sufE2[base + i0] = totE - eexcl; }
        if (i1 < NN) { g_preF2[base + i1] = fexcl + f0; g_sufE2[base + i1] = totE - (eexcl + e0); }
        if (tid == 0) { g_preF2[base + NN] = totF; g_sufE2[base + NN] = 0.f; }
    }

    for (int n = tid; n < NN; n += 512) {
        float thr = -s1[bh*NN + n];
        int lo = 0, hi = NN;
        while (lo < hi) {
            int mid = (lo + hi) >> 1;
            if (s2c[mid] > thr) hi = mid; else lo = mid + 1;
        }
        g_kofn[bh*NN + n] = lo;
    }
    __syncthreads();

    const int c = tid >> 6, o = tid & 63;
    const float* whb = Wh + (size_t)b * NN * FDIM + h * HID + o;

    float cF = 0.f, cE = 0.f;
#pragma unroll 4
    for (int j = 0; j < CH; j++) {
        int i = c*CH + j;
        float w = whb[(size_t)perm[i] * FDIM];
        cF += ff[i] * w;
        cE += fe[i] * w;
    }
    chF[c*HID + o] = cF;
    chE[c*HID + o] = cE;
    __syncthreads();

    float accF = 0.f, accE = 0.f;
    for (int c2 = 0; c2 < c; c2++)       accF += chF[c2*HID + o];
    for (int c2 = c + 1; c2 < NCH; c2++) accE += chE[c2*HID + o];

    size_t base2 = ((size_t)bh*(NN+1))*HID + o;
#pragma unroll 4
    for (int j = 0; j < CH; j++) {
        int i = c*CH + j;
        float w = whb[(size_t)perm[i] * FDIM];
        g_PreF[base2 + (size_t)i*HID] = accF;
        accF += ff[i] * w;
    }
    if (c == NCH - 1) {
        g_PreF[base2 + (size_t)NN*HID] = accF;
        g_SufE[base2 + (size_t)NN*HID] = 0.f;
    }
#pragma unroll 4
    for (int j = CH - 1; j >= 0; j--) {
        int i = c*CH + j;
        float w = whb[(size_t)perm[i] * FDIM];
        accE += fe[i] * w;
        g_SufE[base2 + (size_t)i*HID] = accE;
    }
}

// Output PRE-ROUNDED: hc feeds only the next tf32 GEMM (which previously
// rounded at fragment load) — bitwise identical overall.
__global__ void apply_attn(const float* __restrict__ s1, float* __restrict__ out) {
    int bh = blockIdx.y, h = bh % NH, b = bh / NH;
    int n = blockIdx.x * 4 + (threadIdx.x >> 6);
    int o = threadIdx.x & 63;
    float s1v = s1[bh*NN + n];
    float mx = g_s2max[bh];
    float u = s1v + mx;
    float rmax = u > 0.f ? u : 0.2f * u;
    float E1 = expf(u - rmax);
    float F1 = expf(0.2f * u - rmax);
    int k = g_kofn[bh*NN + n];
    size_t idx = ((size_t)bh*(NN+1) + k)*HID + o;
    float num = E1 * g_SufE[idx] + F1 * g_PreF[idx];
    float den = E1 * g_sufE2[bh*(NN+1) + k] + F1 * g_preF2[bh*(NN+1) + k];
    out[((size_t)(b*NN + n))*FDIM + h*HID + o] = rnd_tf32(num / den);
}

static void run_gat_layer(const float* hin, const float* Bt, const float* att,
                          float* Wh, float* hout, int K) {
    float *s1, *s2;
    cudaGetSymbolAddress((void**)&s1, g_s1);
    cudaGetSymbolAddress((void**)&s2, g_s2);
    tf32_gemm<<<dim3(BN/128, FDIM/64), 128>>>(hin, Bt, nullptr, Wh, FDIM, K, att, s1, s2);
    prep_scan<<<BH, 512>>>(s2, s1, Wh);
    apply_attn<<<dim3(NN/4, BH), 256>>>(s1, hout);
}

extern "C" void kernel_launch(void* const* d_in, const int* in_sizes, int n_in,
                              void* d_out, int out_size) {
    const float* x    = (const float*)d_in[0];
    const float* ip_w = (const float*)d_in[1];
    const float* ip_b = (const float*)d_in[2];
    const float* w0   = (const float*)d_in[3];
    const float* a0   = (const float*)d_in[4];
    const float* w1   = (const float*)d_in[5];
    const float* a1   = (const float*)d_in[6];
    const float* pw   = (const float*)d_in[7];
    const float* pb   = (const float*)d_in[8];
    float* out = (float*)d_out;

    float *h0, *Wh, *hc1, *hc2, *B0t, *B1t, *pwT;
    cudaGetSymbolAddress((void**)&h0,  g_h0);
    cudaGetSymbolAddress((void**)&Wh,  g_Wh);
    cudaGetSymbolAddress((void**)&hc1, g_hc1);
    cudaGetSymbolAddress((void**)&hc2, g_hc2);
    cudaGetSymbolAddress((void**)&B0t, g_B0t);
    cudaGetSymbolAddress((void**)&B1t, g_B1t);
    cudaGetSymbolAddress((void**)&pwT, g_pwT);

    prep_B<<<512, 256>>>(w0, w1, pw);

    // input projection: h0 = x @ ip_w + ip_b  (h0 stored tf32-rounded)
    sgemm<<<dim3(BN/64, HID/64), 256>>>(x, ip_w, ip_b, h0, BN, HID, INDIM);

    run_gat_layer(h0,  B0t, a0, Wh, hc1, HID);   // GAT layer 0
    run_gat_layer(hc1, B1t, a1, Wh, hc2, FDIM);  // GAT layer 1

    // output projection
    tf32_gemm<<<dim3(BN/128, EMB/64), 128>>>(hc2, pwT, pb, out, EMB, FDIM,
                                             nullptr, nullptr, nullptr);
}

// round 13
// speedup vs baseline: 1.5224x; 1.0136x over previous
#include <cuda_runtime.h>
#include <math.h>
#include <stdint.h>

#define BSZ 16
#define NN 768
#define INDIM 16
#define HID 64
#define EMB 128
#define NH 8
#define BN (BSZ*NN)        // 12288
#define FDIM (NH*HID)      // 512
#define BH (BSZ*NH)        // 128
#define BHN (BH*NN)        // 98304
#define CH 96
#define NCH 8              // CH*NCH = 768

// ---- static scratch ----
__device__ float g_h0 [BN*HID];
__device__ float g_Wh [BN*FDIM];
__device__ float g_hc1[BN*FDIM];
__device__ float g_hc2[BN*FDIM];
__device__ float g_s1[BHN], g_s2[BHN];
__device__ int   g_kofn[BHN];
__device__ float g_s2max[BH];
__device__ float g_preF2[BH*(NN+1)], g_sufE2[BH*(NN+1)];
__device__ float g_PreF[(size_t)BH*(NN+1)*HID];
__device__ float g_SufE[(size_t)BH*(NN+1)*HID];
__device__ float g_B0t[FDIM*HID];
__device__ float g_B1t[FDIM*FDIM];
__device__ float g_pwT[EMB*FDIM];

// ===================== HMMA tf32 GEMM (+ fused score) =====================
__device__ __forceinline__ uint32_t smem_u32(const void* p) {
    uint32_t a;
    asm("{ .reg .u64 t; cvta.to.shared.u64 t, %1; cvt.u32.u64 %0, t; }" : "=r"(a) : "l"(p));
    return a;
}
__device__ __forceinline__ uint32_t f2tf(float x) {
    uint32_t u; asm("cvt.rna.tf32.f32 %0, %1;" : "=r"(u) : "f"(x)); return u;
}
__device__ __forceinline__ float rnd_tf32(float x) {       // round-at-producer
    return __uint_as_float(f2tf(x));
}
__device__ __forceinline__ void mma_tf32(float* d, const uint32_t* a, const uint32_t* b) {
    asm volatile("mma.sync.aligned.m16n8k8.row.col.f32.tf32.tf32.f32 "
                 "{%0,%1,%2,%3}, {%4,%5,%6,%7}, {%8,%9}, {%0,%1,%2,%3};"
                 : "+f"(d[0]), "+f"(d[1]), "+f"(d[2]), "+f"(d[3])
                 : "r"(a[0]), "r"(a[1]), "r"(a[2]), "r"(a[3]), "r"(b[0]), "r"(b[1]));
}
#define CP16(dst, src) \
    asm volatile("cp.async.ca.shared.global [%0], [%1], 16;" :: "r"(dst), "l"(src) : "memory")
#define CP_COMMIT()  asm volatile("cp.async.commit_group;" ::: "memory")
#define CP_WAIT0()   asm volatile("cp.async.wait_group 0;" ::: "memory")

__device__ __forceinline__ int swz(int row, int k) {
    return row * 32 + ((((k >> 2) ^ (row & 7)) << 2) | (k & 3));
}

// Operands are PRE-ROUNDED tf32 bit patterns: inner loop is pure LDS.u32 + MMA.
__global__ __launch_bounds__(128)
void tf32_gemm(const float* __restrict__ A, const float* __restrict__ Bt,
               const float* __restrict__ bias, float* __restrict__ C,
               int N, int K,
               const float* __restrict__ att, float* __restrict__ s1out,
               float* __restrict__ s2out) {
    __shared__ float As[2][128 * 32];
    __shared__ float Bs[2][64 * 32];
    __shared__ float sp1[128], sp2[128];
    const int tid = threadIdx.x;
    const int wid = tid >> 5, lane = tid & 31;
    const int r = lane >> 2, cc = lane & 3;
    const int warp_m = (wid & 1) * 64, warp_n = (wid >> 1) * 32;
    const int m0 = blockIdx.x * 128, n0 = blockIdx.y * 64;

    sp1[tid] = 0.f; sp2[tid] = 0.f;

    uint32_t asb[2] = { smem_u32(&As[0][0]), smem_u32(&As[1][0]) };
    uint32_t bsb[2] = { smem_u32(&Bs[0][0]), smem_u32(&Bs[1][0]) };

    float acc[4][4][4] = {};
    const int NC = K >> 5;

    {
#pragma unroll
        for (int j = 0; j < 8; j++) {
            int u = tid + j * 128, row = u >> 3, ch = u & 7;
            CP16(asb[0] + (uint32_t)(row * 32 + ((ch ^ (row & 7)) << 2)) * 4,
                 A + (size_t)(m0 + row) * K + ch * 4);
        }
#pragma unroll
        for (int j = 0; j < 4; j++) {
            int u = tid + j * 128, row = u >> 3, ch = u & 7;
            CP16(bsb[0] + (uint32_t)(row * 32 + ((ch ^ (row & 7)) << 2)) * 4,
                 Bt + (size_t)(n0 + row) * K + ch * 4);
        }
        CP_COMMIT();
    }

    for (int i = 0; i < NC; i++) {
        CP_WAIT0();
        __syncthreads();
        if (i + 1 < NC) {
            int nb = (i + 1) & 1, kc = (i + 1) * 32;
#pragma unroll
            for (int j = 0; j < 8; j++) {
                int u = tid + j * 128, row = u >> 3, ch = u & 7;
                CP16(asb[nb] + (uint32_t)(row * 32 + ((ch ^ (row & 7)) << 2)) * 4,
                     A + (size_t)(m0 + row) * K + kc + ch * 4);
            }
#pragma unroll
            for (int j = 0; j < 4; j++) {
                int u = tid + j * 128, row = u >> 3, ch = u & 7;
                CP16(bsb[nb] + (uint32_t)(row * 32 + ((ch ^ (row & 7)) << 2)) * 4,
                     Bt + (size_t)(n0 + row) * K + kc + ch * 4);
            }
            CP_COMMIT();
        }
        const uint32_t* as = (const uint32_t*)As[i & 1];
        const uint32_t* bs = (const uint32_t*)Bs[i & 1];
#pragma unroll
        for (int ks = 0; ks < 4; ks++) {
            uint32_t af[4][4], bf[4][2];
#pragma unroll
            for (int mt = 0; mt < 4; mt++) {
                int rb = warp_m + mt * 16 + r;
                af[mt][0] = as[swz(rb,     ks * 8 + cc)];
                af[mt][1] = as[swz(rb + 8, ks * 8 + cc)];
                af[mt][2] = as[swz(rb,     ks * 8 + cc + 4)];
                af[mt][3] = as[swz(rb + 8, ks * 8 + cc + 4)];
            }
#pragma unroll
            for (int nt = 0; nt < 4; nt++) {
                int nb = warp_n + nt * 8 + r;
                bf[nt][0] = bs[swz(nb, ks * 8 + cc)];
                bf[nt][1] = bs[swz(nb, ks * 8 + cc + 4)];
            }
#pragma unroll
            for (int mt = 0; mt < 4; mt++)
#pragma unroll
                for (int nt = 0; nt < 4; nt++)
                    mma_tf32(acc[mt][nt], af[mt], bf[nt]);
        }
        __syncthreads();
    }

#pragma unroll
    for (int mt = 0; mt < 4; mt++) {
#pragma unroll
        for (int nt = 0; nt < 4; nt++) {
            int row = m0 + warp_m + mt * 16 + r;
            int col = n0 + warp_n + nt * 8 + cc * 2;
            float bx = 0.f, by = 0.f;
            if (bias) { bx = bias[col]; by = bias[col + 1]; }
            float2 v0 = { acc[mt][nt][0] + bx, acc[mt][nt][1] + by };
            float2 v1 = { acc[mt][nt][2] + bx, acc[mt][nt][3] + by };
            *(float2*)&C[(size_t)row * N + col] = v0;
            *(float2*)&C[(size_t)(row + 8) * N + col] = v1;
        }
    }

    if (att) {
        int h = n0 >> 6;
        const float* a1 = att + h * 2 * HID;
        const float* a2 = a1 + HID;
#pragma unroll
        for (int mt = 0; mt < 4; mt++) {
            float p1a = 0.f, p2a = 0.f, p1b = 0.f, p2b = 0.f;
#pragma unroll
            for (int nt = 0; nt < 4; nt++) {
                int col = warp_n + nt * 8 + cc * 2;
                float a1x = a1[col], a1y = a1[col + 1];
                float a2x = a2[col], a2y = a2[col + 1];
                p1a += acc[mt][nt][0] * a1x + acc[mt][nt][1] * a1y;
                p2a += acc[mt][nt][0] * a2x + acc[mt][nt][1] * a2y;
                p1b += acc[mt][nt][2] * a1x + acc[mt][nt][3] * a1y;
                p2b += acc[mt][nt][2] * a2x + acc[mt][nt][3] * a2y;
            }
#pragma unroll
            for (int off = 1; off <= 2; off <<= 1) {
                p1a += __shfl_xor_sync(0xffffffffu, p1a, off);
                p2a += __shfl_xor_sync(0xffffffffu, p2a, off);
                p1b += __shfl_xor_sync(0xffffffffu, p1b, off);
                p2b += __shfl_xor_sync(0xffffffffu, p2b, off);
            }
            if (cc == 0) {
                int lr = warp_m + mt * 16 + r;
                atomicAdd(&sp1[lr], p1a);     atomicAdd(&sp2[lr], p2a);
                atomicAdd(&sp1[lr + 8], p1b); atomicAdd(&sp2[lr + 8], p2b);
            }
        }
        __syncthreads();
        int gr = m0 + tid;
        int b2 = gr / NN, n2 = gr % NN;
        int bh2 = b2 * NH + h;
        s1out[bh2 * NN + n2] = sp1[tid];
        s2out[bh2 * NN + n2] = sp2[tid];
    }
}

// ===================== non-GEMM kernels =====================

// Weights stored PRE-ROUNDED to tf32 bit patterns.
__global__ void prep_B(const float* __restrict__ w0, const float* __restrict__ w1,
                       const float* __restrict__ pw) {
    int i0 = blockIdx.x * blockDim.x + threadIdx.x;
    int stride = gridDim.x * blockDim.x;
    for (int i = i0; i < FDIM*HID; i += stride) {
        int n = i / HID, f = i % HID;
        g_B0t[i] = rnd_tf32(w0[(n / HID) * (HID*HID) + f * HID + (n % HID)]);
    }
    for (int i = i0; i < FDIM*FDIM; i += stride) {
        int n = i / FDIM, f = i % FDIM;
        g_B1t[i] = rnd_tf32(w1[(n / HID) * (FDIM*HID) + f * HID + (n % HID)]);
    }
    for (int i = i0; i < EMB*FDIM; i += stride) {
        int n = i / FDIM, k = i % FDIM;
        g_pwT[i] = rnd_tf32(pw[k * EMB + n]);
    }
}

// small fp32 SGEMM for the input projection (K=16); output PRE-ROUNDED.
__global__ void sgemm(const float* __restrict__ A, const float* __restrict__ B,
                      const float* __restrict__ bias, float* __restrict__ C,
                      int M, int N, int K) {
    __shared__ float As[16][64];
    __shared__ float Bs[16][64];
    int tid = threadIdx.x;
    int m0 = blockIdx.x * 64, n0 = blockIdx.y * 64;
    int tx = tid & 15, ty = tid >> 4;
    int arow = tid >> 2, acol = (tid & 3) * 4;
    int brow = tid >> 4, bcol = (tid & 15) * 4;
    float acc[4][4] = {};
    for (int kc = 0; kc < K; kc += 16) {
        float4 av = *(const float4*)&A[(size_t)(m0 + arow) * K + kc + acol];
        As[acol+0][arow] = av.x; As[acol+1][arow] = av.y;
        As[acol+2][arow] = av.z; As[acol+3][arow] = av.w;
        *(float4*)&Bs[brow][bcol] = *(const float4*)&B[(size_t)(kc + brow) * N + n0 + bcol];
        __syncthreads();
#pragma unroll
        for (int k = 0; k < 16; k++) {
            float4 a4 = *(float4*)&As[k][ty*4];
            float4 b4 = *(float4*)&Bs[k][tx*4];
            float a[4] = {a4.x, a4.y, a4.z, a4.w};
            float b[4] = {b4.x, b4.y, b4.z, b4.w};
#pragma unroll
            for (int i = 0; i < 4; i++)
#pragma unroll
                for (int j = 0; j < 4; j++) acc[i][j] += a[i] * b[j];
        }
        __syncthreads();
    }
#pragma unroll
    for (int i = 0; i < 4; i++) {
        int m = m0 + ty*4 + i, n = n0 + tx*4;
        float4 v = {rnd_tf32(acc[i][0] + bias[n]),   rnd_tf32(acc[i][1] + bias[n+1]),
                    rnd_tf32(acc[i][2] + bias[n+2]), rnd_tf32(acc[i][3] + bias[n+3])};
        *(float4*)&C[(size_t)m * N + n] = v;
    }
}

// Fused: per (b,h) u64-bitonic sort of s2 + E2/F2 + scalar scans + k(n),
// then chunk sums + INTERLEAVED PreF/SufE table sweeps (2 load streams).
__global__ __launch_bounds__(512)
void prep_scan(const float* __restrict__ s2, const float* __restrict__ s1,
               const float* __restrict__ Wh) {
    __shared__ unsigned long long sv[1024];
    __shared__ float fe[NN], ff[NN], s2c[NN];
    __shared__ int   perm[NN];
    __shared__ float wsE[16], wsF[16];
    __shared__ float chF[NCH*HID], chE[NCH*HID];
    const int bh = blockIdx.x, tid = threadIdx.x;
    const int lane = tid & 31, wrp = tid >> 5;
    const int h = bh % NH, b = bh / NH;

    for (int i = tid; i < 1024; i += 512) {
        if (i < NN) {
            uint32_t bt = __float_as_uint(s2[bh*NN + i]);
            uint32_t key = (bt & 0x80000000u) ? ~bt : (bt | 0x80000000u);
            sv[i] = ((unsigned long long)key << 32) | (unsigned)i;
        } else sv[i] = 0xFFFFFFFFFFFFFFFFull;
    }
    __syncthreads();
    for (int k = 2; k <= 1024; k <<= 1) {
        for (int j = k >> 1; j > 0; j >>= 1) {
            for (int i = tid; i < 1024; i += 512) {
                int ixj = i ^ j;
                if (ixj > i) {
                    bool up = ((i & k) == 0);
                    unsigned long long a = sv[i], bb = sv[ixj];
                    if ((a > bb) == up) { sv[i] = bb; sv[ixj] = a; }
                }
            }
            __syncthreads();
        }
    }
    float mx;
    {
        uint32_t keyN = (uint32_t)(sv[NN-1] >> 32);
        uint32_t bt = (keyN & 0x80000000u) ? (keyN & 0x7FFFFFFFu) : ~keyN;
        mx = __uint_as_float(bt);
    }
    if (tid == 0) g_s2max[bh] = mx;
    for (int i = tid; i < NN; i += 512) {
        unsigned long long p = sv[i];
        uint32_t key = (uint32_t)(p >> 32);
        uint32_t bt = (key & 0x80000000u) ? (key & 0x7FFFFFFFu) : ~key;
        float v = __uint_as_float(bt);
        float d = v - mx;
        float e = expf(d), f = expf(0.2f * d);
        fe[i] = e; ff[i] = f;
        s2c[i] = v;
        perm[i] = (int)(p & 0xFFFFFFFFu);
    }
    __syncthreads();

    {
        int i0 = 2 * tid, i1 = 2 * tid + 1;
        float e0 = (i0 < NN) ? fe[i0] : 0.f, e1 = (i1 < NN) ? fe[i1] : 0.f;
        float f0 = (i0 < NN) ? ff[i0] : 0.f, f1 = (i1 < NN) ? ff[i1] : 0.f;
        float le = e0 + e1, lf = f0 + f1;
        float eI = le, fI = lf;
#pragma unroll
        for (int off = 1; off < 32; off <<= 1) {
            float a = __shfl_up_sync(0xffffffffu, eI, off);
            float bb = __shfl_up_sync(0xffffffffu, fI, off);
            if (lane >= off) { eI += a; fI += bb; }
        }
        if (lane == 31) { wsE[wrp] = eI; wsF[wrp] = fI; }
        __syncthreads();
        if (tid == 0) {
            float a = 0.f, bb = 0.f;
            for (int w = 0; w < 16; w++) { a += wsE[w]; wsE[w] = a; bb += wsF[w]; wsF[w] = bb; }
        }
        __syncthreads();
        float baseE = (wrp > 0) ? wsE[wrp-1] : 0.f;
        float baseF = (wrp > 0) ? wsF[wrp-1] : 0.f;
        float eexcl = baseE + (eI - le);
        float fexcl = baseF + (fI - lf);
        float totE = wsE[15], totF = wsF[15];
        int base = bh * (NN + 1);
        if (i0 < NN) { g_preF2[base + i0] = fexcl;      g_sufE2[base + i0] = totE - eexcl; }
        if (i1 < NN) { g_preF2[base + i1] = fexcl + f0; g_sufE2[base + i1] = totE - (eexcl + e0); }
        if (tid == 0) { g_preF2[base + NN] = totF; g_sufE2[base + NN] = 0.f; }
    }

    for (int n = tid; n < NN; n += 512) {
        float thr = -s1[bh*NN + n];
        int lo = 0, hi = NN;
        while (lo < hi) {
            int mid = (lo + hi) >> 1;
            if (s2c[mid] > thr) hi = mid; else lo = mid + 1;
        }
        g_kofn[bh*NN + n] = lo;
    }
    __syncthreads();

    // ---- phase B: chunk sums, then interleaved fwd/bwd table sweeps ----
    const int c = tid >> 6, o = tid & 63;
    const float* whb = Wh + (size_t)b * NN * FDIM + h * HID + o;

    float cF = 0.f, cE = 0.f;
#pragma unroll 8
    for (int j = 0; j < CH; j++) {
        int i = c*CH + j;
        float w = whb[(size_t)perm[i] * FDIM];
        cF += ff[i] * w;
        cE += fe[i] * w;
    }
    chF[c*HID + o] = cF;
    chE[c*HID + o] = cE;
    __syncthreads();

    float accF = 0.f, accE = 0.f;
    for (int c2 = 0; c2 < c; c2++)       accF += chF[c2*HID + o];
    for (int c2 = c + 1; c2 < NCH; c2++) accE += chE[c2*HID + o];

    size_t base2 = ((size_t)bh*(NN+1))*HID + o;
    // Interleaved sweeps: fwd index iF ascending (PreF exclusive), bwd index iB
    // descending (SufE inclusive-from). Per-sweep accumulation order identical
    // to the sequential version -> bitwise-same tables; 2 independent load
    // streams double the MLP.
#pragma unroll 4
    for (int j = 0; j < CH; j++) {
        int iF = c*CH + j;
        int iB = c*CH + (CH - 1 - j);
        float wF = whb[(size_t)perm[iF] * FDIM];
        float wB = whb[(size_t)perm[iB] * FDIM];
        g_PreF[base2 + (size_t)iF*HID] = accF;
        accF += ff[iF] * wF;
        accE += fe[iB] * wB;
        g_SufE[base2 + (size_t)iB*HID] = accE;
    }
    if (c == NCH - 1) {
        g_PreF[base2 + (size_t)NN*HID] = accF;
        g_SufE[base2 + (size_t)NN*HID] = 0.f;
    }
}

// Output PRE-ROUNDED: hc feeds only the next tf32 GEMM.
__global__ void apply_attn(const float* __restrict__ s1, float* __restrict__ out) {
    int bh = blockIdx.y, h = bh % NH, b = bh / NH;
    int n = blockIdx.x * 4 + (threadIdx.x >> 6);
    int o = threadIdx.x & 63;
    float s1v = s1[bh*NN + n];
    float mx = g_s2max[bh];
    float u = s1v + mx;
    float rmax = u > 0.f ? u : 0.2f * u;
    float E1 = expf(u - rmax);
    float F1 = expf(0.2f * u - rmax);
    int k = g_kofn[bh*NN + n];
    size_t idx = ((size_t)bh*(NN+1) + k)*HID + o;
    float num = E1 * g_SufE[idx] + F1 * g_PreF[idx];
    float den = E1 * g_sufE2[bh*(NN+1) + k] + F1 * g_preF2[bh*(NN+1) + k];
    out[((size_t)(b*NN + n))*FDIM + h*HID + o] = rnd_tf32(num / den);
}

static void run_gat_layer(const float* hin, const float* Bt, const float* att,
                          float* Wh, float* hout, int K) {
    float *s1, *s2;
    cudaGetSymbolAddress((void**)&s1, g_s1);
    cudaGetSymbolAddress((void**)&s2, g_s2);
    tf32_gemm<<<dim3(BN/128, FDIM/64), 128>>>(hin, Bt, nullptr, Wh, FDIM, K, att, s1, s2);
    prep_scan<<<BH, 512>>>(s2, s1, Wh);
    apply_attn<<<dim3(NN/4, BH), 256>>>(s1, hout);
}

extern "C" void kernel_launch(void* const* d_in, const int* in_sizes, int n_in,
                              void* d_out, int out_size) {
    const float* x    = (const float*)d_in[0];
    const float* ip_w = (const float*)d_in[1];
    const float* ip_b = (const float*)d_in[2];
    const float* w0   = (const float*)d_in[3];
    const float* a0   = (const float*)d_in[4];
    const float* w1   = (const float*)d_in[5];
    const float* a1   = (const float*)d_in[6];
    const float* pw   = (const float*)d_in[7];
    const float* pb   = (const float*)d_in[8];
    float* out = (float*)d_out;

    float *h0, *Wh, *hc1, *hc2, *B0t, *B1t, *pwT;
    cudaGetSymbolAddress((void**)&h0,  g_h0);
    cudaGetSymbolAddress((void**)&Wh,  g_Wh);
    cudaGetSymbolAddress((void**)&hc1, g_hc1);
    cudaGetSymbolAddress((void**)&hc2, g_hc2);
    cudaGetSymbolAddress((void**)&B0t, g_B0t);
    cudaGetSymbolAddress((void**)&B1t, g_B1t);
    cudaGetSymbolAddress((void**)&pwT, g_pwT);

    prep_B<<<512, 256>>>(w0, w1, pw);

    // input projection: h0 = x @ ip_w + ip_b  (h0 stored tf32-rounded)
    sgemm<<<dim3(BN/64, HID/64), 256>>>(x, ip_w, ip_b, h0, BN, HID, INDIM);

    run_gat_layer(h0,  B0t, a0, Wh, hc1, HID);   // GAT layer 0
    run_gat_layer(hc1, B1t, a1, Wh, hc2, FDIM);  // GAT layer 1

    // output projection
    tf32_gemm<<<dim3(BN/128, EMB/64), 128>>>(hc2, pwT, pb, out, EMB, FDIM,
                                             nullptr, nullptr, nullptr);
}

// round 14
// speedup vs baseline: 1.6602x; 1.0905x over previous
#include <cuda_runtime.h>
#include <math.h>
#include <stdint.h>

#define BSZ 16
#define NN 768
#define INDIM 16
#define HID 64
#define EMB 128
#define NH 8
#define BN (BSZ*NN)        // 12288
#define FDIM (NH*HID)      // 512
#define BH (BSZ*NH)        // 128
#define BHN (BH*NN)        // 98304
#define CH 48
#define NCH 16             // CH*NCH = 768

// ---- static scratch ----
__device__ float g_h0 [BN*HID];
__device__ float g_Wh [BN*FDIM];
__device__ float g_hc1[BN*FDIM];
__device__ float g_hc2[BN*FDIM];
__device__ float g_s1[BHN], g_s2[BHN];
__device__ int   g_kofn[BHN];
__device__ float g_s2max[BH];
__device__ float g_preF2[BH*(NN+1)], g_sufE2[BH*(NN+1)];
__device__ float g_PreF[(size_t)BH*(NN+1)*HID];
__device__ float g_SufE[(size_t)BH*(NN+1)*HID];
__device__ float g_B0t[FDIM*HID];
__device__ float g_B1t[FDIM*FDIM];
__device__ float g_pwT[EMB*FDIM];

// ===================== HMMA tf32 GEMM (+ fused score) =====================
__device__ __forceinline__ uint32_t smem_u32(const void* p) {
    uint32_t a;
    asm("{ .reg .u64 t; cvta.to.shared.u64 t, %1; cvt.u32.u64 %0, t; }" : "=r"(a) : "l"(p));
    return a;
}
__device__ __forceinline__ uint32_t f2tf(float x) {
    uint32_t u; asm("cvt.rna.tf32.f32 %0, %1;" : "=r"(u) : "f"(x)); return u;
}
__device__ __forceinline__ float rnd_tf32(float x) {       // round-at-producer
    return __uint_as_float(f2tf(x));
}
__device__ __forceinline__ void mma_tf32(float* d, const uint32_t* a, const uint32_t* b) {
    asm volatile("mma.sync.aligned.m16n8k8.row.col.f32.tf32.tf32.f32 "
                 "{%0,%1,%2,%3}, {%4,%5,%6,%7}, {%8,%9}, {%0,%1,%2,%3};"
                 : "+f"(d[0]), "+f"(d[1]), "+f"(d[2]), "+f"(d[3])
                 : "r"(a[0]), "r"(a[1]), "r"(a[2]), "r"(a[3]), "r"(b[0]), "r"(b[1]));
}
#define CP16(dst, src) \
    asm volatile("cp.async.ca.shared.global [%0], [%1], 16;" :: "r"(dst), "l"(src) : "memory")
#define CP_COMMIT()  asm volatile("cp.async.commit_group;" ::: "memory")
#define CP_WAIT0()   asm volatile("cp.async.wait_group 0;" ::: "memory")

__device__ __forceinline__ int swz(int row, int k) {
    return row * 32 + ((((k >> 2) ^ (row & 7)) << 2) | (k & 3));
}

// Operands are PRE-ROUNDED tf32 bit patterns: inner loop is pure LDS.u32 + MMA.
__global__ __launch_bounds__(128)
void tf32_gemm(const float* __restrict__ A, const float* __restrict__ Bt,
               const float* __restrict__ bias, float* __restrict__ C,
               int N, int K,
               const float* __restrict__ att, float* __restrict__ s1out,
               float* __restrict__ s2out) {
    __shared__ float As[2][128 * 32];
    __shared__ float Bs[2][64 * 32];
    __shared__ float sp1[128], sp2[128];
    const int tid = threadIdx.x;
    const int wid = tid >> 5, lane = tid & 31;
    const int r = lane >> 2, cc = lane & 3;
    const int warp_m = (wid & 1) * 64, warp_n = (wid >> 1) * 32;
    const int m0 = blockIdx.x * 128, n0 = blockIdx.y * 64;

    sp1[tid] = 0.f; sp2[tid] = 0.f;

    uint32_t asb[2] = { smem_u32(&As[0][0]), smem_u32(&As[1][0]) };
    uint32_t bsb[2] = { smem_u32(&Bs[0][0]), smem_u32(&Bs[1][0]) };

    float acc[4][4][4] = {};
    const int NC = K >> 5;

    {
#pragma unroll
        for (int j = 0; j < 8; j++) {
            int u = tid + j * 128, row = u >> 3, ch = u & 7;
            CP16(asb[0] + (uint32_t)(row * 32 + ((ch ^ (row & 7)) << 2)) * 4,
                 A + (size_t)(m0 + row) * K + ch * 4);
        }
#pragma unroll
        for (int j = 0; j < 4; j++) {
            int u = tid + j * 128, row = u >> 3, ch = u & 7;
            CP16(bsb[0] + (uint32_t)(row * 32 + ((ch ^ (row & 7)) << 2)) * 4,
                 Bt + (size_t)(n0 + row) * K + ch * 4);
        }
        CP_COMMIT();
    }

    for (int i = 0; i < NC; i++) {
        CP_WAIT0();
        __syncthreads();
        if (i + 1 < NC) {
            int nb = (i + 1) & 1, kc = (i + 1) * 32;
#pragma unroll
            for (int j = 0; j < 8; j++) {
                int u = tid + j * 128, row = u >> 3, ch = u & 7;
                CP16(asb[nb] + (uint32_t)(row * 32 + ((ch ^ (row & 7)) << 2)) * 4,
                     A + (size_t)(m0 + row) * K + kc + ch * 4);
            }
#pragma unroll
            for (int j = 0; j < 4; j++) {
                int u = tid + j * 128, row = u >> 3, ch = u & 7;
                CP16(bsb[nb] + (uint32_t)(row * 32 + ((ch ^ (row & 7)) << 2)) * 4,
                     Bt + (size_t)(n0 + row) * K + kc + ch * 4);
            }
            CP_COMMIT();
        }
        const uint32_t* as = (const uint32_t*)As[i & 1];
        const uint32_t* bs = (const uint32_t*)Bs[i & 1];
#pragma unroll
        for (int ks = 0; ks < 4; ks++) {
            uint32_t af[4][4], bf[4][2];
#pragma unroll
            for (int mt = 0; mt < 4; mt++) {
                int rb = warp_m + mt * 16 + r;
                af[mt][0] = as[swz(rb,     ks * 8 + cc)];
                af[mt][1] = as[swz(rb + 8, ks * 8 + cc)];
                af[mt][2] = as[swz(rb,     ks * 8 + cc + 4)];
                af[mt][3] = as[swz(rb + 8, ks * 8 + cc + 4)];
            }
#pragma unroll
            for (int nt = 0; nt < 4; nt++) {
                int nb = warp_n + nt * 8 + r;
                bf[nt][0] = bs[swz(nb, ks * 8 + cc)];
                bf[nt][1] = bs[swz(nb, ks * 8 + cc + 4)];
            }
#pragma unroll
            for (int mt = 0; mt < 4; mt++)
#pragma unroll
                for (int nt = 0; nt < 4; nt++)
                    mma_tf32(acc[mt][nt], af[mt], bf[nt]);
        }
        __syncthreads();
    }

#pragma unroll
    for (int mt = 0; mt < 4; mt++) {
#pragma unroll
        for (int nt = 0; nt < 4; nt++) {
            int row = m0 + warp_m + mt * 16 + r;
            int col = n0 + warp_n + nt * 8 + cc * 2;
            float bx = 0.f, by = 0.f;
            if (bias) { bx = bias[col]; by = bias[col + 1]; }
            float2 v0 = { acc[mt][nt][0] + bx, acc[mt][nt][1] + by };
            float2 v1 = { acc[mt][nt][2] + bx, acc[mt][nt][3] + by };
            *(float2*)&C[(size_t)row * N + col] = v0;
            *(float2*)&C[(size_t)(row + 8) * N + col] = v1;
        }
    }

    if (att) {
        int h = n0 >> 6;
        const float* a1 = att + h * 2 * HID;
        const float* a2 = a1 + HID;
#pragma unroll
        for (int mt = 0; mt < 4; mt++) {
            float p1a = 0.f, p2a = 0.f, p1b = 0.f, p2b = 0.f;
#pragma unroll
            for (int nt = 0; nt < 4; nt++) {
                int col = warp_n + nt * 8 + cc * 2;
                float a1x = a1[col], a1y = a1[col + 1];
                float a2x = a2[col], a2y = a2[col + 1];
                p1a += acc[mt][nt][0] * a1x + acc[mt][nt][1] * a1y;
                p2a += acc[mt][nt][0] * a2x + acc[mt][nt][1] * a2y;
                p1b += acc[mt][nt][2] * a1x + acc[mt][nt][3] * a1y;
                p2b += acc[mt][nt][2] * a2x + acc[mt][nt][3] * a2y;
            }
#pragma unroll
            for (int off = 1; off <= 2; off <<= 1) {
                p1a += __shfl_xor_sync(0xffffffffu, p1a, off);
                p2a += __shfl_xor_sync(0xffffffffu, p2a, off);
                p1b += __shfl_xor_sync(0xffffffffu, p1b, off);
                p2b += __shfl_xor_sync(0xffffffffu, p2b, off);
            }
            if (cc == 0) {
                int lr = warp_m + mt * 16 + r;
                atomicAdd(&sp1[lr], p1a);     atomicAdd(&sp2[lr], p2a);
                atomicAdd(&sp1[lr + 8], p1b); atomicAdd(&sp2[lr + 8], p2b);
            }
        }
        __syncthreads();
        int gr = m0 + tid;
        int b2 = gr / NN, n2 = gr % NN;
        int bh2 = b2 * NH + h;
        s1out[bh2 * NN + n2] = sp1[tid];
        s2out[bh2 * NN + n2] = sp2[tid];
    }
}

// ===================== non-GEMM kernels =====================

// Weights stored PRE-ROUNDED to tf32 bit patterns.
__global__ void prep_B(const float* __restrict__ w0, const float* __restrict__ w1,
                       const float* __restrict__ pw) {
    int i0 = blockIdx.x * blockDim.x + threadIdx.x;
    int stride = gridDim.x * blockDim.x;
    for (int i = i0; i < FDIM*HID; i += stride) {
        int n = i / HID, f = i % HID;
        g_B0t[i] = rnd_tf32(w0[(n / HID) * (HID*HID) + f * HID + (n % HID)]);
    }
    for (int i = i0; i < FDIM*FDIM; i += stride) {
        int n = i / FDIM, f = i % FDIM;
        g_B1t[i] = rnd_tf32(w1[(n / HID) * (FDIM*HID) + f * HID + (n % HID)]);
    }
    for (int i = i0; i < EMB*FDIM; i += stride) {
        int n = i / FDIM, k = i % FDIM;
        g_pwT[i] = rnd_tf32(pw[k * EMB + n]);
    }
}

// small fp32 SGEMM for the input projection (K=16); output PRE-ROUNDED.
__global__ void sgemm(const float* __restrict__ A, const float* __restrict__ B,
                      const float* __restrict__ bias, float* __restrict__ C,
                      int M, int N, int K) {
    __shared__ float As[16][64];
    __shared__ float Bs[16][64];
    int tid = threadIdx.x;
    int m0 = blockIdx.x * 64, n0 = blockIdx.y * 64;
    int tx = tid & 15, ty = tid >> 4;
    int arow = tid >> 2, acol = (tid & 3) * 4;
    int brow = tid >> 4, bcol = (tid & 15) * 4;
    float acc[4][4] = {};
    for (int kc = 0; kc < K; kc += 16) {
        float4 av = *(const float4*)&A[(size_t)(m0 + arow) * K + kc + acol];
        As[acol+0][arow] = av.x; As[acol+1][arow] = av.y;
        As[acol+2][arow] = av.z; As[acol+3][arow] = av.w;
        *(float4*)&Bs[brow][bcol] = *(const float4*)&B[(size_t)(kc + brow) * N + n0 + bcol];
        __syncthreads();
#pragma unroll
        for (int k = 0; k < 16; k++) {
            float4 a4 = *(float4*)&As[k][ty*4];
            float4 b4 = *(float4*)&Bs[k][tx*4];
            float a[4] = {a4.x, a4.y, a4.z, a4.w};
            float b[4] = {b4.x, b4.y, b4.z, b4.w};
#pragma unroll
            for (int i = 0; i < 4; i++)
#pragma unroll
                for (int j = 0; j < 4; j++) acc[i][j] += a[i] * b[j];
        }
        __syncthreads();
    }
#pragma unroll
    for (int i = 0; i < 4; i++) {
        int m = m0 + ty*4 + i, n = n0 + tx*4;
        float4 v = {rnd_tf32(acc[i][0] + bias[n]),   rnd_tf32(acc[i][1] + bias[n+1]),
                    rnd_tf32(acc[i][2] + bias[n+2]), rnd_tf32(acc[i][3] + bias[n+3])};
        *(float4*)&C[(size_t)m * N + n] = v;
    }
}

// Fused: per (b,h) u64-bitonic sort + E2/F2 + scans + k(n), then 16-chunk
// interleaved PreF/SufE table sweeps. 1024 threads (16 chunks x 64 o).
__global__ __launch_bounds__(1024)
void prep_scan(const float* __restrict__ s2, const float* __restrict__ s1,
               const float* __restrict__ Wh) {
    __shared__ unsigned long long sv[1024];
    __shared__ float fe[NN], ff[NN], s2c[NN];
    __shared__ int   perm[NN];
    __shared__ float wsE[32], wsF[32];
    __shared__ float chF[NCH*HID], chE[NCH*HID];
    const int bh = blockIdx.x, tid = threadIdx.x;
    const int lane = tid & 31, wrp = tid >> 5;
    const int h = bh % NH, b = bh / NH;

    {
        int i = tid;
        if (i < NN) {
            uint32_t bt = __float_as_uint(s2[bh*NN + i]);
            uint32_t key = (bt & 0x80000000u) ? ~bt : (bt | 0x80000000u);
            sv[i] = ((unsigned long long)key << 32) | (unsigned)i;
        } else sv[i] = 0xFFFFFFFFFFFFFFFFull;
    }
    __syncthreads();
    for (int k = 2; k <= 1024; k <<= 1) {
        for (int j = k >> 1; j > 0; j >>= 1) {
            int i = tid;
            int ixj = i ^ j;
            if (ixj > i) {
                bool up = ((i & k) == 0);
                unsigned long long a = sv[i], bb = sv[ixj];
                if ((a > bb) == up) { sv[i] = bb; sv[ixj] = a; }
            }
            __syncthreads();
        }
    }
    float mx;
    {
        uint32_t keyN = (uint32_t)(sv[NN-1] >> 32);
        uint32_t bt = (keyN & 0x80000000u) ? (keyN & 0x7FFFFFFFu) : ~keyN;
        mx = __uint_as_float(bt);
    }
    if (tid == 0) g_s2max[bh] = mx;
    if (tid < NN) {
        int i = tid;
        unsigned long long p = sv[i];
        uint32_t key = (uint32_t)(p >> 32);
        uint32_t bt = (key & 0x80000000u) ? (key & 0x7FFFFFFFu) : ~key;
        float v = __uint_as_float(bt);
        float d = v - mx;
        float e = expf(d), f = expf(0.2f * d);
        fe[i] = e; ff[i] = f;
        s2c[i] = v;
        perm[i] = (int)(p & 0xFFFFFFFFu);
    }
    __syncthreads();

    {   // scans: thread owns elems {2t, 2t+1}; tids >= 384 contribute zeros
        int i0 = 2 * tid, i1 = 2 * tid + 1;
        float e0 = (i0 < NN) ? fe[i0] : 0.f, e1 = (i1 < NN) ? fe[i1] : 0.f;
        float f0 = (i0 < NN) ? ff[i0] : 0.f, f1 = (i1 < NN) ? ff[i1] : 0.f;
        float le = e0 + e1, lf = f0 + f1;
        float eI = le, fI = lf;
#pragma unroll
        for (int off = 1; off < 32; off <<= 1) {
            float a = __shfl_up_sync(0xffffffffu, eI, off);
            float bb = __shfl_up_sync(0xffffffffu, fI, off);
            if (lane >= off) { eI += a; fI += bb; }
        }
        if (lane == 31) { wsE[wrp] = eI; wsF[wrp] = fI; }
        __syncthreads();
        if (tid == 0) {
            float a = 0.f, bb = 0.f;
            for (int w = 0; w < 32; w++) { a += wsE[w]; wsE[w] = a; bb += wsF[w]; wsF[w] = bb; }
        }
        __syncthreads();
        float baseE = (wrp > 0) ? wsE[wrp-1] : 0.f;
        float baseF = (wrp > 0) ? wsF[wrp-1] : 0.f;
        float eexcl = baseE + (eI - le);
        float fexcl = baseF + (fI - lf);
        float totE = wsE[31], totF = wsF[31];
        int base = bh * (NN + 1);
        if (i0 < NN) { g_preF2[base + i0] = fexcl;      g_sufE2[base + i0] = totE - eexcl; }
        if (i1 < NN) { g_preF2[base + i1] = fexcl + f0; g_sufE2[base + i1] = totE - (eexcl + e0); }
        if (tid == 0) { g_preF2[base + NN] = totF; g_sufE2[base + NN] = 0.f; }
    }

    if (tid < NN) {
        int n = tid;
        float thr = -s1[bh*NN + n];
        int lo = 0, hi = NN;
        while (lo < hi) {
            int mid = (lo + hi) >> 1;
            if (s2c[mid] > thr) hi = mid; else lo = mid + 1;
        }
        g_kofn[bh*NN + n] = lo;
    }
    __syncthreads();

    // ---- phase B: 16 chunks x 64 o; chunk sums then interleaved sweeps ----
    const int c = tid >> 6, o = tid & 63;
    const float* whb = Wh + (size_t)b * NN * FDIM + h * HID + o;

    float cF = 0.f, cE = 0.f;
#pragma unroll 8
    for (int j = 0; j < CH; j++) {
        int i = c*CH + j;
        float w = whb[(size_t)perm[i] * FDIM];
        cF += ff[i] * w;
        cE += fe[i] * w;
    }
    chF[c*HID + o] = cF;
    chE[c*HID + o] = cE;
    __syncthreads();

    float accF = 0.f, accE = 0.f;
    for (int c2 = 0; c2 < c; c2++)       accF += chF[c2*HID + o];
    for (int c2 = c + 1; c2 < NCH; c2++) accE += chE[c2*HID + o];

    size_t base2 = ((size_t)bh*(NN+1))*HID + o;
    // Interleaved fwd/bwd sweeps (2 independent load streams, 48 iters).
#pragma unroll 4
    for (int j = 0; j < CH; j++) {
        int iF = c*CH + j;
        int iB = c*CH + (CH - 1 - j);
        float wF = whb[(size_t)perm[iF] * FDIM];
        float wB = whb[(size_t)perm[iB] * FDIM];
        g_PreF[base2 + (size_t)iF*HID] = accF;
        accF += ff[iF] * wF;
        accE += fe[iB] * wB;
        g_SufE[base2 + (size_t)iB*HID] = accE;
    }
    if (c == NCH - 1) {
        g_PreF[base2 + (size_t)NN*HID] = accF;
        g_SufE[base2 + (size_t)NN*HID] = 0.f;
    }
}

// Output PRE-ROUNDED: hc feeds only the next tf32 GEMM.
__global__ void apply_attn(const float* __restrict__ s1, float* __restrict__ out) {
    int bh = blockIdx.y, h = bh % NH, b = bh / NH;
    int n = blockIdx.x * 4 + (threadIdx.x >> 6);
    int o = threadIdx.x & 63;
    float s1v = s1[bh*NN + n];
    float mx = g_s2max[bh];
    float u = s1v + mx;
    float rmax = u > 0.f ? u : 0.2f * u;
    float E1 = expf(u - rmax);
    float F1 = expf(0.2f * u - rmax);
    int k = g_kofn[bh*NN + n];
    size_t idx = ((size_t)bh*(NN+1) + k)*HID + o;
    float num = E1 * g_SufE[idx] + F1 * g_PreF[idx];
    float den = E1 * g_sufE2[bh*(NN+1) + k] + F1 * g_preF2[bh*(NN+1) + k];
    out[((size_t)(b*NN + n))*FDIM + h*HID + o] = rnd_tf32(num / den);
}

static void run_gat_layer(const float* hin, const float* Bt, const float* att,
                          float* Wh, float* hout, int K) {
    float *s1, *s2;
    cudaGetSymbolAddress((void**)&s1, g_s1);
    cudaGetSymbolAddress((void**)&s2, g_s2);
    tf32_gemm<<<dim3(BN/128, FDIM/64), 128>>>(hin, Bt, nullptr, Wh, FDIM, K, att, s1, s2);
    prep_scan<<<BH, 1024>>>(s2, s1, Wh);
    apply_attn<<<dim3(NN/4, BH), 256>>>(s1, hout);
}

extern "C" void kernel_launch(void* const* d_in, const int* in_sizes, int n_in,
                              void* d_out, int out_size) {
    const float* x    = (const float*)d_in[0];
    const float* ip_w = (const float*)d_in[1];
    const float* ip_b = (const float*)d_in[2];
    const float* w0   = (const float*)d_in[3];
    const float* a0   = (const float*)d_in[4];
    const float* w1   = (const float*)d_in[5];
    const float* a1   = (const float*)d_in[6];
    const float* pw   = (const float*)d_in[7];
    const float* pb   = (const float*)d_in[8];
    float* out = (float*)d_out;

    float *h0, *Wh, *hc1, *hc2, *B0t, *B1t, *pwT;
    cudaGetSymbolAddress((void**)&h0,  g_h0);
    cudaGetSymbolAddress((void**)&Wh,  g_Wh);
    cudaGetSymbolAddress((void**)&hc1, g_hc1);
    cudaGetSymbolAddress((void**)&hc2, g_hc2);
    cudaGetSymbolAddress((void**)&B0t, g_B0t);
    cudaGetSymbolAddress((void**)&B1t, g_B1t);
    cudaGetSymbolAddress((void**)&pwT, g_pwT);

    prep_B<<<512, 256>>>(w0, w1, pw);

    // input projection: h0 = x @ ip_w + ip_b  (h0 stored tf32-rounded)
    sgemm<<<dim3(BN/64, HID/64), 256>>>(x, ip_w, ip_b, h0, BN, HID, INDIM);

    run_gat_layer(h0,  B0t, a0, Wh, hc1, HID);   // GAT layer 0
    run_gat_layer(hc1, B1t, a1, Wh, hc2, FDIM);  // GAT layer 1

    // output projection
    tf32_gemm<<<dim3(BN/128, EMB/64), 128>>>(hc2, pwT, pb, out, EMB, FDIM,
                                             nullptr, nullptr, nullptr);
}

// round 15
// speedup vs baseline: 1.9405x; 1.1688x over previous
#include <cuda_runtime.h>
#include <math.h>
#include <stdint.h>

#define BSZ 16
#define NN 768
#define INDIM 16
#define HID 64
#define EMB 128
#define NH 8
#define BN (BSZ*NN)        // 12288
#define FDIM (NH*HID)      // 512
#define BH (BSZ*NH)        // 128
#define BHN (BH*NN)        // 98304
#define CH 48
#define NCH 16             // CH*NCH = 768

// ---- static scratch ----
__device__ float g_h0 [BN*HID];
__device__ float g_Wh [BN*FDIM];
__device__ float g_hc1[BN*FDIM];
__device__ float g_hc2[BN*FDIM];
__device__ float g_s1[BHN], g_s2[BHN];
__device__ int   g_kofn[BHN];
__device__ float g_E1[BHN], g_F1[BHN], g_ivd[BHN];
__device__ float g_PreF[(size_t)BH*(NN+1)*HID];
__device__ float g_SufE[(size_t)BH*(NN+1)*HID];
__device__ float g_B0t[FDIM*HID];
__device__ float g_B1t[FDIM*FDIM];
__device__ float g_pwT[EMB*FDIM];

// ===================== HMMA tf32 GEMM (+ fused score) =====================
__device__ __forceinline__ uint32_t smem_u32(const void* p) {
    uint32_t a;
    asm("{ .reg .u64 t; cvta.to.shared.u64 t, %1; cvt.u32.u64 %0, t; }" : "=r"(a) : "l"(p));
    return a;
}
__device__ __forceinline__ uint32_t f2tf(float x) {
    uint32_t u; asm("cvt.rna.tf32.f32 %0, %1;" : "=r"(u) : "f"(x)); return u;
}
__device__ __forceinline__ float rnd_tf32(float x) {       // round-at-producer
    return __uint_as_float(f2tf(x));
}
__device__ __forceinline__ void mma_tf32(float* d, const uint32_t* a, const uint32_t* b) {
    asm volatile("mma.sync.aligned.m16n8k8.row.col.f32.tf32.tf32.f32 "
                 "{%0,%1,%2,%3}, {%4,%5,%6,%7}, {%8,%9}, {%0,%1,%2,%3};"
                 : "+f"(d[0]), "+f"(d[1]), "+f"(d[2]), "+f"(d[3])
                 : "r"(a[0]), "r"(a[1]), "r"(a[2]), "r"(a[3]), "r"(b[0]), "r"(b[1]));
}
#define CP16(dst, src) \
    asm volatile("cp.async.ca.shared.global [%0], [%1], 16;" :: "r"(dst), "l"(src) : "memory")
#define CP_COMMIT()  asm volatile("cp.async.commit_group;" ::: "memory")
#define CP_WAIT0()   asm volatile("cp.async.wait_group 0;" ::: "memory")

__device__ __forceinline__ int swz(int row, int k) {
    return row * 32 + ((((k >> 2) ^ (row & 7)) << 2) | (k & 3));
}

// Operands are PRE-ROUNDED tf32 bit patterns: inner loop is pure LDS.u32 + MMA.
__global__ __launch_bounds__(128)
void tf32_gemm(const float* __restrict__ A, const float* __restrict__ Bt,
               const float* __restrict__ bias, float* __restrict__ C,
               int N, int K,
               const float* __restrict__ att, float* __restrict__ s1out,
               float* __restrict__ s2out) {
    __shared__ float As[2][128 * 32];
    __shared__ float Bs[2][64 * 32];
    __shared__ float sp1[128], sp2[128];
    const int tid = threadIdx.x;
    const int wid = tid >> 5, lane = tid & 31;
    const int r = lane >> 2, cc = lane & 3;
    const int warp_m = (wid & 1) * 64, warp_n = (wid >> 1) * 32;
    const int m0 = blockIdx.x * 128, n0 = blockIdx.y * 64;

    sp1[tid] = 0.f; sp2[tid] = 0.f;

    uint32_t asb[2] = { smem_u32(&As[0][0]), smem_u32(&As[1][0]) };
    uint32_t bsb[2] = { smem_u32(&Bs[0][0]), smem_u32(&Bs[1][0]) };

    float acc[4][4][4] = {};
    const int NC = K >> 5;

    {
#pragma unroll
        for (int j = 0; j < 8; j++) {
            int u = tid + j * 128, row = u >> 3, ch = u & 7;
            CP16(asb[0] + (uint32_t)(row * 32 + ((ch ^ (row & 7)) << 2)) * 4,
                 A + (size_t)(m0 + row) * K + ch * 4);
        }
#pragma unroll
        for (int j = 0; j < 4; j++) {
            int u = tid + j * 128, row = u >> 3, ch = u & 7;
            CP16(bsb[0] + (uint32_t)(row * 32 + ((ch ^ (row & 7)) << 2)) * 4,
                 Bt + (size_t)(n0 + row) * K + ch * 4);
        }
        CP_COMMIT();
    }

    for (int i = 0; i < NC; i++) {
        CP_WAIT0();
        __syncthreads();
        if (i + 1 < NC) {
            int nb = (i + 1) & 1, kc = (i + 1) * 32;
#pragma unroll
            for (int j = 0; j < 8; j++) {
                int u = tid + j * 128, row = u >> 3, ch = u & 7;
                CP16(asb[nb] + (uint32_t)(row * 32 + ((ch ^ (row & 7)) << 2)) * 4,
                     A + (size_t)(m0 + row) * K + kc + ch * 4);
            }
#pragma unroll
            for (int j = 0; j < 4; j++) {
                int u = tid + j * 128, row = u >> 3, ch = u & 7;
                CP16(bsb[nb] + (uint32_t)(row * 32 + ((ch ^ (row & 7)) << 2)) * 4,
                     Bt + (size_t)(n0 + row) * K + kc + ch * 4);
            }
            CP_COMMIT();
        }
        const uint32_t* as = (const uint32_t*)As[i & 1];
        const uint32_t* bs = (const uint32_t*)Bs[i & 1];
#pragma unroll
        for (int ks = 0; ks < 4; ks++) {
            uint32_t af[4][4], bf[4][2];
#pragma unroll
            for (int mt = 0; mt < 4; mt++) {
                int rb = warp_m + mt * 16 + r;
                af[mt][0] = as[swz(rb,     ks * 8 + cc)];
                af[mt][1] = as[swz(rb + 8, ks * 8 + cc)];
                af[mt][2] = as[swz(rb,     ks * 8 + cc + 4)];
                af[mt][3] = as[swz(rb + 8, ks * 8 + cc + 4)];
            }
#pragma unroll
            for (int nt = 0; nt < 4; nt++) {
                int nb = warp_n + nt * 8 + r;
                bf[nt][0] = bs[swz(nb, ks * 8 + cc)];
                bf[nt][1] = bs[swz(nb, ks * 8 + cc + 4)];
            }
#pragma unroll
            for (int mt = 0; mt < 4; mt++)
#pragma unroll
                for (int nt = 0; nt < 4; nt++)
                    mma_tf32(acc[mt][nt], af[mt], bf[nt]);
        }
        __syncthreads();
    }

#pragma unroll
    for (int mt = 0; mt < 4; mt++) {
#pragma unroll
        for (int nt = 0; nt < 4; nt++) {
            int row = m0 + warp_m + mt * 16 + r;
            int col = n0 + warp_n + nt * 8 + cc * 2;
            float bx = 0.f, by = 0.f;
            if (bias) { bx = bias[col]; by = bias[col + 1]; }
            float2 v0 = { acc[mt][nt][0] + bx, acc[mt][nt][1] + by };
            float2 v1 = { acc[mt][nt][2] + bx, acc[mt][nt][3] + by };
            *(float2*)&C[(size_t)row * N + col] = v0;
            *(float2*)&C[(size_t)(row + 8) * N + col] = v1;
        }
    }

    if (att) {
        int h = n0 >> 6;
        const float* a1 = att + h * 2 * HID;
        const float* a2 = a1 + HID;
#pragma unroll
        for (int mt = 0; mt < 4; mt++) {
            float p1a = 0.f, p2a = 0.f, p1b = 0.f, p2b = 0.f;
#pragma unroll
            for (int nt = 0; nt < 4; nt++) {
                int col = warp_n + nt * 8 + cc * 2;
                float a1x = a1[col], a1y = a1[col + 1];
                float a2x = a2[col], a2y = a2[col + 1];
                p1a += acc[mt][nt][0] * a1x + acc[mt][nt][1] * a1y;
                p2a += acc[mt][nt][0] * a2x + acc[mt][nt][1] * a2y;
                p1b += acc[mt][nt][2] * a1x + acc[mt][nt][3] * a1y;
                p2b += acc[mt][nt][2] * a2x + acc[mt][nt][3] * a2y;
            }
#pragma unroll
            for (int off = 1; off <= 2; off <<= 1) {
                p1a += __shfl_xor_sync(0xffffffffu, p1a, off);
                p2a += __shfl_xor_sync(0xffffffffu, p2a, off);
                p1b += __shfl_xor_sync(0xffffffffu, p1b, off);
                p2b += __shfl_xor_sync(0xffffffffu, p2b, off);
            }
            if (cc == 0) {
                int lr = warp_m + mt * 16 + r;
                atomicAdd(&sp1[lr], p1a);     atomicAdd(&sp2[lr], p2a);
                atomicAdd(&sp1[lr + 8], p1b); atomicAdd(&sp2[lr + 8], p2b);
            }
        }
        __syncthreads();
        int gr = m0 + tid;
        int b2 = gr / NN, n2 = gr % NN;
        int bh2 = b2 * NH + h;
        s1out[bh2 * NN + n2] = sp1[tid];
        s2out[bh2 * NN + n2] = sp2[tid];
    }
}

// ===================== non-GEMM kernels =====================

// Weights stored PRE-ROUNDED to tf32 bit patterns.
__global__ void prep_B(const float* __restrict__ w0, const float* __restrict__ w1,
                       const float* __restrict__ pw) {
    int i0 = blockIdx.x * blockDim.x + threadIdx.x;
    int stride = gridDim.x * blockDim.x;
    for (int i = i0; i < FDIM*HID; i += stride) {
        int n = i / HID, f = i % HID;
        g_B0t[i] = rnd_tf32(w0[(n / HID) * (HID*HID) + f * HID + (n % HID)]);
    }
    for (int i = i0; i < FDIM*FDIM; i += stride) {
        int n = i / FDIM, f = i % FDIM;
        g_B1t[i] = rnd_tf32(w1[(n / HID) * (FDIM*HID) + f * HID + (n % HID)]);
    }
    for (int i = i0; i < EMB*FDIM; i += stride) {
        int n = i / FDIM, k = i % FDIM;
        g_pwT[i] = rnd_tf32(pw[k * EMB + n]);
    }
}

// small fp32 SGEMM for the input projection (K=16); output PRE-ROUNDED.
__global__ void sgemm(const float* __restrict__ A, const float* __restrict__ B,
                      const float* __restrict__ bias, float* __restrict__ C,
                      int M, int N, int K) {
    __shared__ float As[16][64];
    __shared__ float Bs[16][64];
    int tid = threadIdx.x;
    int m0 = blockIdx.x * 64, n0 = blockIdx.y * 64;
    int tx = tid & 15, ty = tid >> 4;
    int arow = tid >> 2, acol = (tid & 3) * 4;
    int brow = tid >> 4, bcol = (tid & 15) * 4;
    float acc[4][4] = {};
    for (int kc = 0; kc < K; kc += 16) {
        float4 av = *(const float4*)&A[(size_t)(m0 + arow) * K + kc + acol];
        As[acol+0][arow] = av.x; As[acol+1][arow] = av.y;
        As[acol+2][arow] = av.z; As[acol+3][arow] = av.w;
        *(float4*)&Bs[brow][bcol] = *(const float4*)&B[(size_t)(kc + brow) * N + n0 + bcol];
        __syncthreads();
#pragma unroll
        for (int k = 0; k < 16; k++) {
            float4 a4 = *(float4*)&As[k][ty*4];
            float4 b4 = *(float4*)&Bs[k][tx*4];
            float a[4] = {a4.x, a4.y, a4.z, a4.w};
            float b[4] = {b4.x, b4.y, b4.z, b4.w};
#pragma unroll
            for (int i = 0; i < 4; i++)
#pragma unroll
                for (int j = 0; j < 4; j++) acc[i][j] += a[i] * b[j];
        }
        __syncthreads();
    }
#pragma unroll
    for (int i = 0; i < 4; i++) {
        int m = m0 + ty*4 + i, n = n0 + tx*4;
        float4 v = {rnd_tf32(acc[i][0] + bias[n]),   rnd_tf32(acc[i][1] + bias[n+1]),
                    rnd_tf32(acc[i][2] + bias[n+2]), rnd_tf32(acc[i][3] + bias[n+3])};
        *(float4*)&C[(size_t)m * N + n] = v;
    }
}

// Fused: per (b,h) u64-bitonic sort + E2/F2 + scans (kept in smem) + per-n
// k/E1/F1/ivd precompute, then 16-chunk interleaved PreF/SufE table sweeps.
__global__ __launch_bounds__(1024)
void prep_scan(const float* __restrict__ s2, const float* __restrict__ s1,
               const float* __restrict__ Wh) {
    __shared__ unsigned long long sv[1024];
    __shared__ float fe[NN], ff[NN], s2c[NN];
    __shared__ float sF2[NN+1], sE2[NN+1];
    __shared__ int   perm[NN];
    __shared__ float wsE[32], wsF[32];
    __shared__ float chF[NCH*HID], chE[NCH*HID];
    const int bh = blockIdx.x, tid = threadIdx.x;
    const int lane = tid & 31, wrp = tid >> 5;
    const int h = bh % NH, b = bh / NH;

    {
        int i = tid;
        if (i < NN) {
            uint32_t bt = __float_as_uint(s2[bh*NN + i]);
            uint32_t key = (bt & 0x80000000u) ? ~bt : (bt | 0x80000000u);
            sv[i] = ((unsigned long long)key << 32) | (unsigned)i;
        } else sv[i] = 0xFFFFFFFFFFFFFFFFull;
    }
    __syncthreads();
    for (int k = 2; k <= 1024; k <<= 1) {
        for (int j = k >> 1; j > 0; j >>= 1) {
            int i = tid;
            int ixj = i ^ j;
            if (ixj > i) {
                bool up = ((i & k) == 0);
                unsigned long long a = sv[i], bb = sv[ixj];
                if ((a > bb) == up) { sv[i] = bb; sv[ixj] = a; }
            }
            __syncthreads();
        }
    }
    float mx;
    {
        uint32_t keyN = (uint32_t)(sv[NN-1] >> 32);
        uint32_t bt = (keyN & 0x80000000u) ? (keyN & 0x7FFFFFFFu) : ~keyN;
        mx = __uint_as_float(bt);
    }
    if (tid < NN) {
        int i = tid;
        unsigned long long p = sv[i];
        uint32_t key = (uint32_t)(p >> 32);
        uint32_t bt = (key & 0x80000000u) ? (key & 0x7FFFFFFFu) : ~key;
        float v = __uint_as_float(bt);
        float d = v - mx;
        float e = expf(d), f = expf(0.2f * d);
        fe[i] = e; ff[i] = f;
        s2c[i] = v;
        perm[i] = (int)(p & 0xFFFFFFFFu);
    }
    __syncthreads();

    {   // scans: thread owns elems {2t, 2t+1}; results kept in smem only
        int i0 = 2 * tid, i1 = 2 * tid + 1;
        float e0 = (i0 < NN) ? fe[i0] : 0.f, e1 = (i1 < NN) ? fe[i1] : 0.f;
        float f0 = (i0 < NN) ? ff[i0] : 0.f, f1 = (i1 < NN) ? ff[i1] : 0.f;
        float le = e0 + e1, lf = f0 + f1;
        float eI = le, fI = lf;
#pragma unroll
        for (int off = 1; off < 32; off <<= 1) {
            float a = __shfl_up_sync(0xffffffffu, eI, off);
            float bb = __shfl_up_sync(0xffffffffu, fI, off);
            if (lane >= off) { eI += a; fI += bb; }
        }
        if (lane == 31) { wsE[wrp] = eI; wsF[wrp] = fI; }
        __syncthreads();
        if (tid == 0) {
            float a = 0.f, bb = 0.f;
            for (int w = 0; w < 32; w++) { a += wsE[w]; wsE[w] = a; bb += wsF[w]; wsF[w] = bb; }
        }
        __syncthreads();
        float baseE = (wrp > 0) ? wsE[wrp-1] : 0.f;
        float baseF = (wrp > 0) ? wsF[wrp-1] : 0.f;
        float eexcl = baseE + (eI - le);
        float fexcl = baseF + (fI - lf);
        float totE = wsE[31], totF = wsF[31];
        if (i0 < NN) { sF2[i0] = fexcl;      sE2[i0] = totE - eexcl; }
        if (i1 < NN) { sF2[i1] = fexcl + f0; sE2[i1] = totE - (eexcl + e0); }
        if (tid == 0) { sF2[NN] = totF; sE2[NN] = 0.f; }
    }
    __syncthreads();

    // per-n: k + hoisted E1/F1/ivd (was per-element in apply_attn)
    if (tid < NN) {
        int n = tid;
        float s1v = s1[bh*NN + n];
        float thr = -s1v;
        int lo = 0, hi = NN;
        while (lo < hi) {
            int mid = (lo + hi) >> 1;
            if (s2c[mid] > thr) hi = mid; else lo = mid + 1;
        }
        float u = s1v + mx;
        float rm = u > 0.f ? u : 0.2f * u;
        float E1 = expf(u - rm), F1 = expf(0.2f * u - rm);
        float den = E1 * sE2[lo] + F1 * sF2[lo];
        g_kofn[bh*NN + n] = lo;
        g_E1[bh*NN + n] = E1;
        g_F1[bh*NN + n] = F1;
        g_ivd[bh*NN + n] = 1.f / den;
    }
    __syncthreads();

    // ---- phase B: 16 chunks x 64 o; chunk sums then interleaved sweeps ----
    const int c = tid >> 6, o = tid & 63;
    const float* whb = Wh + (size_t)b * NN * FDIM + h * HID + o;

    float cF = 0.f, cE = 0.f;
#pragma unroll 8
    for (int j = 0; j < CH; j++) {
        int i = c*CH + j;
        float w = whb[(size_t)perm[i] * FDIM];
        cF += ff[i] * w;
        cE += fe[i] * w;
    }
    chF[c*HID + o] = cF;
    chE[c*HID + o] = cE;
    __syncthreads();

    float accF = 0.f, accE = 0.f;
    for (int c2 = 0; c2 < c; c2++)       accF += chF[c2*HID + o];
    for (int c2 = c + 1; c2 < NCH; c2++) accE += chE[c2*HID + o];

    size_t base2 = ((size_t)bh*(NN+1))*HID + o;
    // Interleaved fwd/bwd sweeps (2 independent load streams, 48 iters).
#pragma unroll 4
    for (int j = 0; j < CH; j++) {
        int iF = c*CH + j;
        int iB = c*CH + (CH - 1 - j);
        float wF = whb[(size_t)perm[iF] * FDIM];
        float wB = whb[(size_t)perm[iB] * FDIM];
        g_PreF[base2 + (size_t)iF*HID] = accF;
        accF += ff[iF] * wF;
        accE += fe[iB] * wB;
        g_SufE[base2 + (size_t)iB*HID] = accE;
    }
    if (c == NCH - 1) {
        g_PreF[base2 + (size_t)NN*HID] = accF;
        g_SufE[base2 + (size_t)NN*HID] = 0.f;
    }
}

// Pure streaming combine: no transcendentals, float4 I/O. Output PRE-ROUNDED.
// grid (NN/16, BH), block 256: thread -> (n = 16/block, 4 o's each).
__global__ __launch_bounds__(256)
void apply_attn(float* __restrict__ out) {
    int bh = blockIdx.y, h = bh % NH, b = bh / NH;
    int n = blockIdx.x * 16 + (threadIdx.x >> 4);
    int o4 = (threadIdx.x & 15) * 4;
    int gi = bh * NN + n;
    float E1 = g_E1[gi], F1 = g_F1[gi], ivd = g_ivd[gi];
    int k = g_kofn[gi];
    size_t idx = ((size_t)bh*(NN+1) + k)*HID + o4;
    float4 S = *(const float4*)&g_SufE[idx];
    float4 P = *(const float4*)&g_PreF[idx];
    float4 v;
    v.x = rnd_tf32((E1 * S.x + F1 * P.x) * ivd);
    v.y = rnd_tf32((E1 * S.y + F1 * P.y) * ivd);
    v.z = rnd_tf32((E1 * S.z + F1 * P.z) * ivd);
    v.w = rnd_tf32((E1 * S.w + F1 * P.w) * ivd);
    *(float4*)&out[((size_t)(b*NN + n))*FDIM + h*HID + o4] = v;
}

static void run_gat_layer(const float* hin, const float* Bt, const float* att,
                          float* Wh, float* hout, int K) {
    float *s1, *s2;
    cudaGetSymbolAddress((void**)&s1, g_s1);
    cudaGetSymbolAddress((void**)&s2, g_s2);
    tf32_gemm<<<dim3(BN/128, FDIM/64), 128>>>(hin, Bt, nullptr, Wh, FDIM, K, att, s1, s2);
    prep_scan<<<BH, 1024>>>(s2, s1, Wh);
    apply_attn<<<dim3(NN/16, BH), 256>>>(hout);
}

extern "C" void kernel_launch(void* const* d_in, const int* in_sizes, int n_in,
                              void* d_out, int out_size) {
    const float* x    = (const float*)d_in[0];
    const float* ip_w = (const float*)d_in[1];
    const float* ip_b = (const float*)d_in[2];
    const float* w0   = (const float*)d_in[3];
    const float* a0   = (const float*)d_in[4];
    const float* w1   = (const float*)d_in[5];
    const float* a1   = (const float*)d_in[6];
    const float* pw   = (const float*)d_in[7];
    const float* pb   = (const float*)d_in[8];
    float* out = (float*)d_out;

    float *h0, *Wh, *hc1, *hc2, *B0t, *B1t, *pwT;
    cudaGetSymbolAddress((void**)&h0,  g_h0);
    cudaGetSymbolAddress((void**)&Wh,  g_Wh);
    cudaGetSymbolAddress((void**)&hc1, g_hc1);
    cudaGetSymbolAddress((void**)&hc2, g_hc2);
    cudaGetSymbolAddress((void**)&B0t, g_B0t);
    cudaGetSymbolAddress((void**)&B1t, g_B1t);
    cudaGetSymbolAddress((void**)&pwT, g_pwT);

    prep_B<<<512, 256>>>(w0, w1, pw);

    // input projection: h0 = x @ ip_w + ip_b  (h0 stored tf32-rounded)
    sgemm<<<dim3(BN/64, HID/64), 256>>>(x, ip_w, ip_b, h0, BN, HID, INDIM);

    run_gat_layer(h0,  B0t, a0, Wh, hc1, HID);   // GAT layer 0
    run_gat_layer(hc1, B1t, a1, Wh, hc2, FDIM);  // GAT layer 1

    // output projection
    tf32_gemm<<<dim3(BN/128, EMB/64), 128>>>(hc2, pwT, pb, out, EMB, FDIM,
                                             nullptr, nullptr, nullptr);
}